// round 1
// baseline (speedup 1.0000x reference)
#include <cuda_runtime.h>

#define NROWS 65536
#define NDIMS 512
#define KDIM  512
#define MKNOT 200

// Scratch (device globals: allocation-free kernel_launch).
// g_data0T holds data0^T (K x N) after GEMM1, then t = (y - data0)^T after spline.
__device__ float g_data0T[(size_t)KDIM * NROWS];
__device__ float g_logd[(size_t)KDIM * NROWS];

// ---------------------------------------------------------------------------
// GEMM1: C[m, n] = sum_d A[d, m] * data[n, d]   (C = g_data0T, 512 x 65536)
// Block tile 128(m) x 128(n), k-step 8, 256 threads, 8x8 per thread.
// ---------------------------------------------------------------------------
__global__ __launch_bounds__(256) void gemm1_kernel(const float* __restrict__ data,
                                                    const float* __restrict__ A) {
    __shared__ float As[8][132];  // As[dd][m_local]
    __shared__ float Bs[8][132];  // Bs[dd][n_local]

    const int tid = threadIdx.x;
    const int m0 = blockIdx.y * 128;
    const int n0 = blockIdx.x * 128;
    const int tx = tid & 15;   // n sub-tile
    const int ty = tid >> 4;   // m sub-tile

    const int a_dd = tid >> 5;          // 0..7
    const int a_m4 = (tid & 31) << 2;   // 0,4,...,124
    const int b_nl = tid >> 1;          // 0..127
    const int b_d4 = (tid & 1) << 2;    // 0 or 4

    float acc[8][8];
    #pragma unroll
    for (int i = 0; i < 8; ++i)
        #pragma unroll
        for (int j = 0; j < 8; ++j) acc[i][j] = 0.f;

    for (int d0 = 0; d0 < NDIMS; d0 += 8) {
        // As[dd][m] = A[(d0+dd)*KDIM + m0+m]  (coalesced along m)
        float4 av = *reinterpret_cast<const float4*>(&A[(size_t)(d0 + a_dd) * KDIM + m0 + a_m4]);
        *reinterpret_cast<float4*>(&As[a_dd][a_m4]) = av;
        // Bs[dd][n] = data[(n0+n)*NDIMS + d0+dd]  (vector load along d, transposed store)
        float4 bv = *reinterpret_cast<const float4*>(&data[(size_t)(n0 + b_nl) * NDIMS + d0 + b_d4]);
        Bs[b_d4 + 0][b_nl] = bv.x;
        Bs[b_d4 + 1][b_nl] = bv.y;
        Bs[b_d4 + 2][b_nl] = bv.z;
        Bs[b_d4 + 3][b_nl] = bv.w;
        __syncthreads();

        #pragma unroll
        for (int dd = 0; dd < 8; ++dd) {
            float a[8], b[8];
            #pragma unroll
            for (int i = 0; i < 8; ++i) a[i] = As[dd][ty * 8 + i];
            #pragma unroll
            for (int j = 0; j < 8; ++j) b[j] = Bs[dd][tx * 8 + j];
            #pragma unroll
            for (int i = 0; i < 8; ++i)
                #pragma unroll
                for (int j = 0; j < 8; ++j) acc[i][j] = fmaf(a[i], b[j], acc[i][j]);
        }
        __syncthreads();
    }

    #pragma unroll
    for (int i = 0; i < 8; ++i) {
        const int m = m0 + ty * 8 + i;
        float* dst = &g_data0T[(size_t)m * NROWS + n0 + tx * 8];
        *reinterpret_cast<float4*>(dst)     = make_float4(acc[i][0], acc[i][1], acc[i][2], acc[i][3]);
        *reinterpret_cast<float4*>(dst + 4) = make_float4(acc[i][4], acc[i][5], acc[i][6], acc[i][7]);
    }
}

// ---------------------------------------------------------------------------
// Spline: per element x = data0T[k, n]:
//   searchsorted (left) on xx[k,:], RQ-spline y & logd; linear tails outside.
// Writes t = y - x in place over g_data0T, logd to g_logd.
// One block per (k, 256-row tile); knots staged in shared.
// ---------------------------------------------------------------------------
__global__ __launch_bounds__(256) void spline_kernel(const float* __restrict__ xx,
                                                     const float* __restrict__ yy,
                                                     const float* __restrict__ delta) {
    __shared__ float sxx[MKNOT], syy[MKNOT], sdl[MKNOT];
    const int k = blockIdx.x;
    const int n = blockIdx.y * 256 + threadIdx.x;

    if (threadIdx.x < MKNOT) {
        sxx[threadIdx.x] = xx[(size_t)k * MKNOT + threadIdx.x];
        syy[threadIdx.x] = yy[(size_t)k * MKNOT + threadIdx.x];
        sdl[threadIdx.x] = delta[(size_t)k * MKNOT + threadIdx.x];
    }
    __syncthreads();

    const size_t idx_g = (size_t)k * NROWS + n;
    const float x = g_data0T[idx_g];

    // searchsorted, side='left': first index where sxx[idx] >= x
    int lo = 0, hi = MKNOT;
    while (lo < hi) {
        int mid = (lo + hi) >> 1;
        if (sxx[mid] < x) lo = mid + 1; else hi = mid;
    }
    const bool below = (lo == 0);
    const bool above = (lo == MKNOT);
    const int b = min(max(lo, 1), MKNOT - 1) - 1;

    const float xk  = sxx[b],   xk1 = sxx[b + 1];
    const float yk  = syy[b],   yk1 = syy[b + 1];
    const float dk  = sdl[b],   dk1 = sdl[b + 1];
    const float dx = xk1 - xk;
    const float dy = yk1 - yk;
    const float s  = dy / dx;
    float xi = (x - xk) / dx;
    xi = fminf(fmaxf(xi, 0.f), 1.f);
    const float xi1 = 1.f - xi;
    const float denom = s + (dk1 + dk - 2.f * s) * xi * xi1;
    float y    = yk + dy * (s * xi * xi + dk * xi * xi1) / denom;
    const float num = dk1 * xi * xi + 2.f * s * xi * xi1 + dk * xi1 * xi1;
    float logd = logf((s * s) * num / (denom * denom));

    if (below) {
        y    = syy[0] + sdl[0] * (x - sxx[0]);
        logd = logf(sdl[0]);
    }
    if (above) {
        y    = syy[MKNOT - 1] + sdl[MKNOT - 1] * (x - sxx[MKNOT - 1]);
        logd = logf(sdl[MKNOT - 1]);
    }

    g_data0T[idx_g] = y - x;   // t = y - data0 (in place)
    g_logd[idx_g]   = logd;
}

// ---------------------------------------------------------------------------
// logj[n] = sum_k g_logd[k, n]  (deterministic, coalesced)
// ---------------------------------------------------------------------------
__global__ __launch_bounds__(256) void reduce_kernel(float* __restrict__ logj) {
    const int n = blockIdx.x * 256 + threadIdx.x;
    float s0 = 0.f, s1 = 0.f, s2 = 0.f, s3 = 0.f;
    #pragma unroll 4
    for (int k = 0; k < KDIM; k += 4) {
        s0 += g_logd[(size_t)(k + 0) * NROWS + n];
        s1 += g_logd[(size_t)(k + 1) * NROWS + n];
        s2 += g_logd[(size_t)(k + 2) * NROWS + n];
        s3 += g_logd[(size_t)(k + 3) * NROWS + n];
    }
    logj[n] = (s0 + s1) + (s2 + s3);
}

// ---------------------------------------------------------------------------
// GEMM2: out[n, d] = data[n, d] + sum_kk t[kk, n] * A[d, kk]
// t = g_data0T (K x N). Block tile 128(n) x 128(d), k-step 8.
// ---------------------------------------------------------------------------
__global__ __launch_bounds__(256) void gemm2_kernel(const float* __restrict__ data,
                                                    const float* __restrict__ A,
                                                    float* __restrict__ out) {
    __shared__ float Ts[8][132];  // Ts[kk][n_local]
    __shared__ float Bs[8][132];  // Bs[kk][d_local]

    const int tid = threadIdx.x;
    const int n0 = blockIdx.x * 128;
    const int d0 = blockIdx.y * 128;
    const int tx = tid & 15;   // d sub-tile
    const int ty = tid >> 4;   // n sub-tile

    const int t_kk = tid >> 5;          // 0..7
    const int t_n4 = (tid & 31) << 2;   // 0..124
    const int b_dl = tid >> 1;          // 0..127
    const int b_k4 = (tid & 1) << 2;    // 0 or 4

    float acc[8][8];
    #pragma unroll
    for (int i = 0; i < 8; ++i)
        #pragma unroll
        for (int j = 0; j < 8; ++j) acc[i][j] = 0.f;

    for (int kk0 = 0; kk0 < KDIM; kk0 += 8) {
        // Ts[kk][n] = t[(kk0+kk)*NROWS + n0+n]  (coalesced along n)
        float4 tv = *reinterpret_cast<const float4*>(&g_data0T[(size_t)(kk0 + t_kk) * NROWS + n0 + t_n4]);
        *reinterpret_cast<float4*>(&Ts[t_kk][t_n4]) = tv;
        // Bs[kk][d] = A[(d0+d)*KDIM + kk0+kk]  (vector load along kk, transposed store)
        float4 bv = *reinterpret_cast<const float4*>(&A[(size_t)(d0 + b_dl) * KDIM + kk0 + b_k4]);
        Bs[b_k4 + 0][b_dl] = bv.x;
        Bs[b_k4 + 1][b_dl] = bv.y;
        Bs[b_k4 + 2][b_dl] = bv.z;
        Bs[b_k4 + 3][b_dl] = bv.w;
        __syncthreads();

        #pragma unroll
        for (int kk = 0; kk < 8; ++kk) {
            float a[8], b[8];
            #pragma unroll
            for (int i = 0; i < 8; ++i) a[i] = Ts[kk][ty * 8 + i];
            #pragma unroll
            for (int j = 0; j < 8; ++j) b[j] = Bs[kk][tx * 8 + j];
            #pragma unroll
            for (int i = 0; i < 8; ++i)
                #pragma unroll
                for (int j = 0; j < 8; ++j) acc[i][j] = fmaf(a[i], b[j], acc[i][j]);
        }
        __syncthreads();
    }

    #pragma unroll
    for (int i = 0; i < 8; ++i) {
        const int n = n0 + ty * 8 + i;
        const size_t base = (size_t)n * NDIMS + d0 + tx * 8;
        float4 dv0 = *reinterpret_cast<const float4*>(&data[base]);
        float4 dv1 = *reinterpret_cast<const float4*>(&data[base + 4]);
        float4 o0 = make_float4(acc[i][0] + dv0.x, acc[i][1] + dv0.y,
                                acc[i][2] + dv0.z, acc[i][3] + dv0.w);
        float4 o1 = make_float4(acc[i][4] + dv1.x, acc[i][5] + dv1.y,
                                acc[i][6] + dv1.z, acc[i][7] + dv1.w);
        *reinterpret_cast<float4*>(&out[base])     = o0;
        *reinterpret_cast<float4*>(&out[base + 4]) = o1;
    }
}

// ---------------------------------------------------------------------------
extern "C" void kernel_launch(void* const* d_in, const int* in_sizes, int n_in,
                              void* d_out, int out_size) {
    const float* data  = (const float*)d_in[0];  // (65536, 512)
    const float* A     = (const float*)d_in[1];  // (512, 512)
    const float* xx    = (const float*)d_in[2];  // (512, 200)
    const float* yy    = (const float*)d_in[3];  // (512, 200)
    const float* delta = (const float*)d_in[4];  // (512, 200)
    float* out = (float*)d_out;                  // [out (N*NDIM) | logj (N)]

    // 1) data0^T = (data @ A)^T
    gemm1_kernel<<<dim3(NROWS / 128, KDIM / 128), 256>>>(data, A);
    // 2) spline: t = y - data0 (in place), logd scratch
    spline_kernel<<<dim3(KDIM, NROWS / 256), 256>>>(xx, yy, delta);
    // 3) logj = sum_k logd
    reduce_kernel<<<NROWS / 256, 256>>>(out + (size_t)NROWS * NDIMS);
    // 4) out = data + t^T @ A^T
    gemm2_kernel<<<dim3(NROWS / 128, NDIMS / 128), 256>>>(data, A, out);
}

// round 5
// speedup vs baseline: 2.2136x; 2.2136x over previous
#include <cuda_runtime.h>
#include <cuda_bf16.h>
#include <cstdint>

#define NROWS 65536
#define NDIMS 512
#define KDIM  512
#define MKNOT 200

// ---------------------------------------------------------------------------
// Device scratch (allocation-free)
// ---------------------------------------------------------------------------
__device__ __align__(16) float         g_x[(size_t)KDIM * NROWS];       // data0^T (K x N)
__device__ __align__(16) __nv_bfloat16 g_data_hi[(size_t)NROWS * NDIMS];
__device__ __align__(16) __nv_bfloat16 g_data_lo[(size_t)NROWS * NDIMS];
__device__ __align__(16) __nv_bfloat16 g_t_hi[(size_t)NROWS * KDIM];    // (N x K)
__device__ __align__(16) __nv_bfloat16 g_t_lo[(size_t)NROWS * KDIM];
__device__ __align__(16) __nv_bfloat16 g_A_hi[KDIM * NDIMS];            // [d][k]
__device__ __align__(16) __nv_bfloat16 g_A_lo[KDIM * NDIMS];
__device__ __align__(16) __nv_bfloat16 g_AT_hi[KDIM * NDIMS];           // [k][d]
__device__ __align__(16) __nv_bfloat16 g_AT_lo[KDIM * NDIMS];
__device__ __align__(16) float         g_partial[32 * NROWS];

// ---------------------------------------------------------------------------
// PTX helpers (sm_80-level: legal on baseline compute_103 target)
// ---------------------------------------------------------------------------
__device__ __forceinline__ uint32_t smem_u32(const void* p) {
    uint32_t a;
    asm("{ .reg .u64 t; cvta.to.shared.u64 t, %1; cvt.u32.u64 %0, t; }" : "=r"(a) : "l"(p));
    return a;
}
#define CP_ASYNC16(dst, src) \
    asm volatile("cp.async.cg.shared.global [%0], [%1], 16;" :: "r"(dst), "l"(src))
#define CP_COMMIT() asm volatile("cp.async.commit_group;" ::: "memory")
#define CP_WAIT(n)  asm volatile("cp.async.wait_group %0;" :: "n"(n) : "memory")

__device__ __forceinline__ void ldsm_x4(uint32_t* r, uint32_t addr) {
    asm volatile("ldmatrix.sync.aligned.m8n8.x4.shared.b16 {%0,%1,%2,%3}, [%4];"
                 : "=r"(r[0]), "=r"(r[1]), "=r"(r[2]), "=r"(r[3]) : "r"(addr));
}
__device__ __forceinline__ void mma16816(float* d, const uint32_t* a, const uint32_t* b) {
    asm volatile(
        "mma.sync.aligned.m16n8k16.row.col.f32.bf16.bf16.f32 "
        "{%0,%1,%2,%3}, {%4,%5,%6,%7}, {%8,%9}, {%0,%1,%2,%3};"
        : "+f"(d[0]), "+f"(d[1]), "+f"(d[2]), "+f"(d[3])
        : "r"(a[0]), "r"(a[1]), "r"(a[2]), "r"(a[3]), "r"(b[0]), "r"(b[1]));
}

// ---------------------------------------------------------------------------
// Split decomposition
// ---------------------------------------------------------------------------
__global__ __launch_bounds__(256) void decomp_data_kernel(const float* __restrict__ data) {
    size_t i = ((size_t)blockIdx.x * 256 + threadIdx.x) * 4;
    float4 v = *reinterpret_cast<const float4*>(data + i);
    __nv_bfloat16 h0 = __float2bfloat16(v.x), h1 = __float2bfloat16(v.y);
    __nv_bfloat16 h2 = __float2bfloat16(v.z), h3 = __float2bfloat16(v.w);
    __nv_bfloat16 l0 = __float2bfloat16(v.x - __bfloat162float(h0));
    __nv_bfloat16 l1 = __float2bfloat16(v.y - __bfloat162float(h1));
    __nv_bfloat16 l2 = __float2bfloat16(v.z - __bfloat162float(h2));
    __nv_bfloat16 l3 = __float2bfloat16(v.w - __bfloat162float(h3));
    *reinterpret_cast<__nv_bfloat162*>(g_data_hi + i)     = __nv_bfloat162(h0, h1);
    *reinterpret_cast<__nv_bfloat162*>(g_data_hi + i + 2) = __nv_bfloat162(h2, h3);
    *reinterpret_cast<__nv_bfloat162*>(g_data_lo + i)     = __nv_bfloat162(l0, l1);
    *reinterpret_cast<__nv_bfloat162*>(g_data_lo + i + 2) = __nv_bfloat162(l2, l3);
}

__global__ __launch_bounds__(256) void decomp_A_kernel(const float* __restrict__ A) {
    int i = blockIdx.x * 256 + threadIdx.x;
    float v = A[i];
    __nv_bfloat16 h = __float2bfloat16(v);
    __nv_bfloat16 l = __float2bfloat16(v - __bfloat162float(h));
    g_A_hi[i] = h;
    g_A_lo[i] = l;
    int d = i >> 9, k = i & 511;
    g_AT_hi[k * 512 + d] = h;
    g_AT_lo[k * 512 + d] = l;
}

// ---------------------------------------------------------------------------
// HMMA GEMM core: D[128(m),128(n)] = sum over K'=1536 (3 bf16 phases of 512).
// A-operand rows m (k-contig, stride 512); B-operand rows n (k-contig, 512).
// smem: double buffer [buf][A 16KB | B 16KB]; rows = 128B, XOR-swizzled.
// Epilogue leaves D in smem as float sD[n][m] stride 132.
// ---------------------------------------------------------------------------
#define GEMM_SMEM 67584   // max(2*32KB operands, 128*132*4 epilogue)

__device__ __forceinline__ void issue_tile(uint32_t sbase, int buf, int c, int tid,
        const __nv_bfloat16* aHi, const __nv_bfloat16* aLo,
        const __nv_bfloat16* bHi, const __nv_bfloat16* bLo) {
    const int ph = c >> 3;
    const int koff = (c & 7) * 64;
    const __nv_bfloat16* a = (ph < 2) ? aHi : aLo;
    const __nv_bfloat16* b = (ph == 1) ? bLo : bHi;
    uint32_t abase = sbase + buf * 32768;
    uint32_t bbase = abase + 16384;
    #pragma unroll
    for (int it = 0; it < 4; ++it) {
        int i = tid + it * 256;
        int r = i >> 3, cc = i & 7;
        CP_ASYNC16(abase + r * 128 + ((cc ^ (r & 7)) << 4),
                   a + (size_t)r * 512 + koff + cc * 8);
    }
    #pragma unroll
    for (int it = 0; it < 4; ++it) {
        int i = tid + it * 256;
        int r = i >> 3, cc = i & 7;
        CP_ASYNC16(bbase + r * 128 + ((cc ^ (r & 7)) << 4),
                   b + (size_t)r * 512 + koff + cc * 8);
    }
}

__device__ __forceinline__ void compute_tile(uint32_t sbase, int buf, int lane,
                                             int wm, int wn, float acc[4][4][4]) {
    uint32_t abase = sbase + buf * 32768;
    uint32_t bbase = abase + 16384;
    const int grp = lane >> 3;
    #pragma unroll
    for (int s = 0; s < 4; ++s) {
        uint32_t af[4][4], bf[4][2];
        #pragma unroll
        for (int mt = 0; mt < 4; ++mt) {
            int rr = wm * 64 + mt * 16 + (lane & 7) + ((grp & 1) << 3);
            int cc = s * 2 + (grp >> 1);
            ldsm_x4(af[mt], abase + rr * 128 + ((cc ^ (rr & 7)) << 4));
        }
        #pragma unroll
        for (int nt2 = 0; nt2 < 2; ++nt2) {
            int rr = wn * 32 + nt2 * 16 + (lane & 7) + ((grp >> 1) << 3);
            int cc = s * 2 + (grp & 1);
            uint32_t tmp[4];
            ldsm_x4(tmp, bbase + rr * 128 + ((cc ^ (rr & 7)) << 4));
            bf[nt2 * 2][0] = tmp[0]; bf[nt2 * 2][1] = tmp[1];
            bf[nt2 * 2 + 1][0] = tmp[2]; bf[nt2 * 2 + 1][1] = tmp[3];
        }
        #pragma unroll
        for (int mt = 0; mt < 4; ++mt)
            #pragma unroll
            for (int nt = 0; nt < 4; ++nt)
                mma16816(acc[mt][nt], af[mt], bf[nt]);
    }
}

__device__ __forceinline__ void gemm_core(const __nv_bfloat16* aHi, const __nv_bfloat16* aLo,
                                          const __nv_bfloat16* bHi, const __nv_bfloat16* bLo,
                                          char* smem) {
    const int tid = threadIdx.x;
    const int lane = tid & 31, wid = tid >> 5;
    const int wm = wid & 1, wn = wid >> 1;
    uint32_t sbase = smem_u32(smem);

    float acc[4][4][4];
    #pragma unroll
    for (int mt = 0; mt < 4; ++mt)
        #pragma unroll
        for (int nt = 0; nt < 4; ++nt)
            #pragma unroll
            for (int r = 0; r < 4; ++r) acc[mt][nt][r] = 0.f;

    issue_tile(sbase, 0, 0, tid, aHi, aLo, bHi, bLo);
    CP_COMMIT();
    int buf = 0;
    for (int c = 0; c < 24; ++c) {
        if (c + 1 < 24) {
            issue_tile(sbase, buf ^ 1, c + 1, tid, aHi, aLo, bHi, bLo);
            CP_COMMIT();
            CP_WAIT(1);
        } else {
            CP_WAIT(0);
        }
        __syncthreads();
        compute_tile(sbase, buf, lane, wm, wn, acc);
        __syncthreads();
        buf ^= 1;
    }

    // Stage D into smem transposed: sD[n][m], stride 132
    float* sD = (float*)smem;
    #pragma unroll
    for (int mt = 0; mt < 4; ++mt)
        #pragma unroll
        for (int nt = 0; nt < 4; ++nt) {
            int r0 = wm * 64 + mt * 16 + (lane >> 2);
            int c0 = wn * 32 + nt * 8 + (lane & 3) * 2;
            sD[(c0    ) * 132 + r0    ] = acc[mt][nt][0];
            sD[(c0 + 1) * 132 + r0    ] = acc[mt][nt][1];
            sD[(c0    ) * 132 + r0 + 8] = acc[mt][nt][2];
            sD[(c0 + 1) * 132 + r0 + 8] = acc[mt][nt][3];
        }
    __syncthreads();
}

// ---------------------------------------------------------------------------
// GEMM1: g_x[k, n] = sum_d data[n, d] * A[d, k]   (m = n rows, n-dim = k)
// ---------------------------------------------------------------------------
__global__ __launch_bounds__(256) void gemm1_kernel() {
    extern __shared__ char smem[];
    const int k0 = blockIdx.x * 128;
    const int n0 = blockIdx.y * 128;
    gemm_core(g_data_hi + (size_t)n0 * 512, g_data_lo + (size_t)n0 * 512,
              g_AT_hi + (size_t)k0 * 512, g_AT_lo + (size_t)k0 * 512, smem);
    const float* sD = (const float*)smem;
    const int tid = threadIdx.x;
    #pragma unroll
    for (int it = 0; it < 16; ++it) {
        int idx = tid + it * 256;
        int nn = idx >> 5, mm = (idx & 31) * 4;
        float4 v = *reinterpret_cast<const float4*>(sD + nn * 132 + mm);
        *reinterpret_cast<float4*>(&g_x[(size_t)(k0 + nn) * NROWS + n0 + mm]) = v;
    }
}

// ---------------------------------------------------------------------------
// GEMM2: out[n, d] = data[n, d] + sum_k t[n, k] * A[d, k]  (m = d rows, n-dim = n)
// ---------------------------------------------------------------------------
__global__ __launch_bounds__(256) void gemm2_kernel(const float* __restrict__ data,
                                                    float* __restrict__ out) {
    extern __shared__ char smem[];
    const int d0 = blockIdx.x * 128;
    const int n0 = blockIdx.y * 128;
    gemm_core(g_A_hi + (size_t)d0 * 512, g_A_lo + (size_t)d0 * 512,
              g_t_hi + (size_t)n0 * 512, g_t_lo + (size_t)n0 * 512, smem);
    const float* sD = (const float*)smem;
    const int tid = threadIdx.x;
    #pragma unroll
    for (int it = 0; it < 16; ++it) {
        int idx = tid + it * 256;
        int nn = idx >> 5, mm = (idx & 31) * 4;
        size_t gi = (size_t)(n0 + nn) * NDIMS + d0 + mm;
        float4 v = *reinterpret_cast<const float4*>(sD + nn * 132 + mm);
        float4 dv = *reinterpret_cast<const float4*>(data + gi);
        v.x += dv.x; v.y += dv.y; v.z += dv.z; v.w += dv.w;
        *reinterpret_cast<float4*>(out + gi) = v;
    }
}

// ---------------------------------------------------------------------------
// Spline + transpose: reads g_x (K,N); writes t = y - x as bf16 hi/lo (N,K);
// per-block partial logj into g_partial. Block: 16 k x 1024 n. Grid (32, 64).
// ---------------------------------------------------------------------------
__global__ __launch_bounds__(256) void spline_kernel(const float* __restrict__ xx,
                                                     const float* __restrict__ yy,
                                                     const float* __restrict__ delta) {
    __shared__ float sxx[16 * 200], syy[16 * 200], sdl[16 * 200];
    __shared__ __align__(16) __nv_bfloat16 sth[64 * 20], stl[64 * 20];
    __shared__ float sred[256];

    const int kg = blockIdx.x;
    const int ng = blockIdx.y;
    const int k0 = kg * 16;
    const int tid = threadIdx.x;

    for (int i = tid; i < 16 * 200; i += 256) {
        int kl = i / 200, m = i - kl * 200;
        size_t gi = (size_t)(k0 + kl) * MKNOT + m;
        sxx[i] = xx[gi]; syy[i] = yy[gi]; sdl[i] = delta[gi];
    }
    __syncthreads();

    const int nl = tid & 63;
    const int kgrp = tid >> 6;

    for (int s = 0; s < 16; ++s) {
        const int n = ng * 1024 + s * 64 + nl;
        float acc = 0.f;
        #pragma unroll
        for (int r = 0; r < 4; ++r) {
            const int kl = r * 4 + kgrp;
            const float* kx = sxx + kl * 200;
            const float* ky = syy + kl * 200;
            const float* kd = sdl + kl * 200;
            const float x = g_x[(size_t)(k0 + kl) * NROWS + n];

            int lo = 0, hi = MKNOT;
            while (lo < hi) {
                int mid = (lo + hi) >> 1;
                if (kx[mid] < x) lo = mid + 1; else hi = mid;
            }
            const bool below = (lo == 0);
            const bool above = (lo == MKNOT);
            const int b = min(max(lo, 1), MKNOT - 1) - 1;

            const float xk = kx[b], xk1 = kx[b + 1];
            const float yk = ky[b], yk1 = ky[b + 1];
            const float dk = kd[b], dk1 = kd[b + 1];
            const float dxk = xk1 - xk;
            const float dyk = yk1 - yk;
            const float sl = dyk / dxk;
            float xi = (x - xk) / dxk;
            xi = fminf(fmaxf(xi, 0.f), 1.f);
            const float xi1 = 1.f - xi;
            const float denom = sl + (dk1 + dk - 2.f * sl) * xi * xi1;
            float y = yk + dyk * (sl * xi * xi + dk * xi * xi1) / denom;
            const float num = dk1 * xi * xi + 2.f * sl * xi * xi1 + dk * xi1 * xi1;
            float logd = logf((sl * sl) * num / (denom * denom));
            if (below) { y = ky[0] + kd[0] * (x - kx[0]); logd = logf(kd[0]); }
            if (above) { y = ky[MKNOT - 1] + kd[MKNOT - 1] * (x - kx[MKNOT - 1]); logd = logf(kd[MKNOT - 1]); }

            const float t = y - x;
            acc += logd;
            __nv_bfloat16 h = __float2bfloat16(t);
            __nv_bfloat16 l = __float2bfloat16(t - __bfloat162float(h));
            sth[nl * 20 + kl] = h;
            stl[nl * 20 + kl] = l;
        }
        sred[tid] = acc;
        __syncthreads();

        {
            const int row = tid >> 2, q = tid & 3;
            uint2 hv = *reinterpret_cast<const uint2*>(sth + row * 20 + q * 4);
            uint2 lv = *reinterpret_cast<const uint2*>(stl + row * 20 + q * 4);
            size_t go = (size_t)(ng * 1024 + s * 64 + row) * KDIM + k0 + q * 4;
            *reinterpret_cast<uint2*>(g_t_hi + go) = hv;
            *reinterpret_cast<uint2*>(g_t_lo + go) = lv;
        }
        if (tid < 64) {
            float p = sred[tid] + sred[64 + tid] + sred[128 + tid] + sred[192 + tid];
            g_partial[(size_t)kg * NROWS + ng * 1024 + s * 64 + tid] = p;
        }
        __syncthreads();
    }
}

__global__ __launch_bounds__(256) void reduce_kernel(float* __restrict__ logj) {
    const int n = blockIdx.x * 256 + threadIdx.x;
    float s = 0.f;
    #pragma unroll
    for (int g = 0; g < 32; ++g) s += g_partial[(size_t)g * NROWS + n];
    logj[n] = s;
}

// ---------------------------------------------------------------------------
extern "C" void kernel_launch(void* const* d_in, const int* in_sizes, int n_in,
                              void* d_out, int out_size) {
    (void)in_sizes; (void)n_in; (void)out_size;
    const float* data  = (const float*)d_in[0];
    const float* A     = (const float*)d_in[1];
    const float* xx    = (const float*)d_in[2];
    const float* yy    = (const float*)d_in[3];
    const float* delta = (const float*)d_in[4];
    float* out  = (float*)d_out;
    float* logj = out + (size_t)NROWS * NDIMS;

    cudaFuncSetAttribute(gemm1_kernel, cudaFuncAttributeMaxDynamicSharedMemorySize, GEMM_SMEM);
    cudaFuncSetAttribute(gemm2_kernel, cudaFuncAttributeMaxDynamicSharedMemorySize, GEMM_SMEM);

    decomp_data_kernel<<<((size_t)NROWS * NDIMS) / 1024, 256>>>(data);
    decomp_A_kernel<<<(KDIM * NDIMS) / 256, 256>>>(A);
    gemm1_kernel<<<dim3(4, NROWS / 128), 256, GEMM_SMEM>>>();
    spline_kernel<<<dim3(32, 64), 256>>>(xx, yy, delta);
    reduce_kernel<<<NROWS / 256, 256>>>(logj);
    gemm2_kernel<<<dim3(4, NROWS / 128), 256, GEMM_SMEM>>>(data, out);
}

// round 7
// speedup vs baseline: 2.3356x; 1.0551x over previous
#include <cuda_runtime.h>
#include <cuda_bf16.h>
#include <cstdint>

#define NROWS 65536
#define NDIMS 512
#define KDIM  512
#define MKNOT 200
#define LUTN  1024
#define LUT_SCALE (1024.0f / 12.0f)

// ---------------------------------------------------------------------------
// Device scratch (allocation-free)
// ---------------------------------------------------------------------------
__device__ __align__(16) float         g_x[(size_t)KDIM * NROWS];       // data0^T (K x N)
__device__ __align__(16) __nv_bfloat16 g_data_hi[(size_t)NROWS * NDIMS];
__device__ __align__(16) __nv_bfloat16 g_data_lo[(size_t)NROWS * NDIMS];
__device__ __align__(16) __nv_bfloat16 g_t_hi[(size_t)NROWS * KDIM];    // (N x K)
__device__ __align__(16) __nv_bfloat16 g_t_lo[(size_t)NROWS * KDIM];
__device__ __align__(16) __nv_bfloat16 g_A_hi[KDIM * NDIMS];            // [d][k]
__device__ __align__(16) __nv_bfloat16 g_A_lo[KDIM * NDIMS];
__device__ __align__(16) __nv_bfloat16 g_AT_hi[KDIM * NDIMS];           // [k][d]
__device__ __align__(16) __nv_bfloat16 g_AT_lo[KDIM * NDIMS];
__device__ __align__(16) float         g_partial[64 * NROWS];
__device__ __align__(16) uint8_t       g_lut[(size_t)KDIM * LUTN];

// ---------------------------------------------------------------------------
// PTX helpers (sm_80-level: legal on baseline compute_103 target)
// ---------------------------------------------------------------------------
__device__ __forceinline__ uint32_t smem_u32(const void* p) {
    uint32_t a;
    asm("{ .reg .u64 t; cvta.to.shared.u64 t, %1; cvt.u32.u64 %0, t; }" : "=r"(a) : "l"(p));
    return a;
}
#define CP_ASYNC16(dst, src) \
    asm volatile("cp.async.cg.shared.global [%0], [%1], 16;" :: "r"(dst), "l"(src))
#define CP_COMMIT() asm volatile("cp.async.commit_group;" ::: "memory")
#define CP_WAIT(n)  asm volatile("cp.async.wait_group %0;" :: "n"(n) : "memory")

__device__ __forceinline__ void ldsm_x4(uint32_t* r, uint32_t addr) {
    asm volatile("ldmatrix.sync.aligned.m8n8.x4.shared.b16 {%0,%1,%2,%3}, [%4];"
                 : "=r"(r[0]), "=r"(r[1]), "=r"(r[2]), "=r"(r[3]) : "r"(addr));
}
__device__ __forceinline__ void mma16816(float* d, const uint32_t* a, const uint32_t* b) {
    asm volatile(
        "mma.sync.aligned.m16n8k16.row.col.f32.bf16.bf16.f32 "
        "{%0,%1,%2,%3}, {%4,%5,%6,%7}, {%8,%9}, {%0,%1,%2,%3};"
        : "+f"(d[0]), "+f"(d[1]), "+f"(d[2]), "+f"(d[3])
        : "r"(a[0]), "r"(a[1]), "r"(a[2]), "r"(a[3]), "r"(b[0]), "r"(b[1]));
}

// ---------------------------------------------------------------------------
// Split decomposition
// ---------------------------------------------------------------------------
__global__ __launch_bounds__(256) void decomp_data_kernel(const float* __restrict__ data) {
    size_t i = ((size_t)blockIdx.x * 256 + threadIdx.x) * 4;
    float4 v = *reinterpret_cast<const float4*>(data + i);
    __nv_bfloat16 h0 = __float2bfloat16(v.x), h1 = __float2bfloat16(v.y);
    __nv_bfloat16 h2 = __float2bfloat16(v.z), h3 = __float2bfloat16(v.w);
    __nv_bfloat16 l0 = __float2bfloat16(v.x - __bfloat162float(h0));
    __nv_bfloat16 l1 = __float2bfloat16(v.y - __bfloat162float(h1));
    __nv_bfloat16 l2 = __float2bfloat16(v.z - __bfloat162float(h2));
    __nv_bfloat16 l3 = __float2bfloat16(v.w - __bfloat162float(h3));
    *reinterpret_cast<__nv_bfloat162*>(g_data_hi + i)     = __nv_bfloat162(h0, h1);
    *reinterpret_cast<__nv_bfloat162*>(g_data_hi + i + 2) = __nv_bfloat162(h2, h3);
    *reinterpret_cast<__nv_bfloat162*>(g_data_lo + i)     = __nv_bfloat162(l0, l1);
    *reinterpret_cast<__nv_bfloat162*>(g_data_lo + i + 2) = __nv_bfloat162(l2, l3);
}

__global__ __launch_bounds__(256) void decomp_A_kernel(const float* __restrict__ A) {
    int i = blockIdx.x * 256 + threadIdx.x;
    float v = A[i];
    __nv_bfloat16 h = __float2bfloat16(v);
    __nv_bfloat16 l = __float2bfloat16(v - __bfloat162float(h));
    g_A_hi[i] = h;
    g_A_lo[i] = l;
    int d = i >> 9, k = i & 511;
    g_AT_hi[k * 512 + d] = h;
    g_AT_lo[k * 512 + d] = l;
}

// ---------------------------------------------------------------------------
// LUT build: for each k, lut[j] = searchsorted_left(xx[k,:], -4 + j*12/1024).
// Cell width (12/1024) < min knot spacing (0.5*8/199) => <=1 knot per cell.
// ---------------------------------------------------------------------------
__global__ __launch_bounds__(256) void lut_kernel(const float* __restrict__ xx) {
    __shared__ float sx[MKNOT];
    const int k = blockIdx.x;
    const int tid = threadIdx.x;
    if (tid < MKNOT) sx[tid] = xx[(size_t)k * MKNOT + tid];
    __syncthreads();
    for (int j = tid; j < LUTN; j += 256) {
        const float gx = -4.0f + (float)j * (12.0f / LUTN);
        int lo = 0, hi = MKNOT;
        while (lo < hi) {
            int mid = (lo + hi) >> 1;
            if (sx[mid] < gx) lo = mid + 1; else hi = mid;
        }
        g_lut[(size_t)k * LUTN + j] = (uint8_t)lo;
    }
}

// ---------------------------------------------------------------------------
// HMMA GEMM core: D[128,128], K'=1536, 3 bf16 phases.
// ---------------------------------------------------------------------------
#define GEMM_SMEM 67584

__device__ __forceinline__ void issue_tile(uint32_t sbase, int buf, int c, int tid,
        const __nv_bfloat16* aHi, const __nv_bfloat16* aLo,
        const __nv_bfloat16* bHi, const __nv_bfloat16* bLo) {
    const int ph = c >> 3;
    const int koff = (c & 7) * 64;
    const __nv_bfloat16* a = (ph < 2) ? aHi : aLo;
    const __nv_bfloat16* b = (ph == 1) ? bLo : bHi;
    uint32_t abase = sbase + buf * 32768;
    uint32_t bbase = abase + 16384;
    #pragma unroll
    for (int it = 0; it < 4; ++it) {
        int i = tid + it * 256;
        int r = i >> 3, cc = i & 7;
        CP_ASYNC16(abase + r * 128 + ((cc ^ (r & 7)) << 4),
                   a + (size_t)r * 512 + koff + cc * 8);
    }
    #pragma unroll
    for (int it = 0; it < 4; ++it) {
        int i = tid + it * 256;
        int r = i >> 3, cc = i & 7;
        CP_ASYNC16(bbase + r * 128 + ((cc ^ (r & 7)) << 4),
                   b + (size_t)r * 512 + koff + cc * 8);
    }
}

__device__ __forceinline__ void compute_tile(uint32_t sbase, int buf, int lane,
                                             int wm, int wn, float acc[4][4][4]) {
    uint32_t abase = sbase + buf * 32768;
    uint32_t bbase = abase + 16384;
    const int grp = lane >> 3;
    #pragma unroll
    for (int s = 0; s < 4; ++s) {
        uint32_t af[4][4], bf[4][2];
        #pragma unroll
        for (int mt = 0; mt < 4; ++mt) {
            int rr = wm * 64 + mt * 16 + (lane & 7) + ((grp & 1) << 3);
            int cc = s * 2 + (grp >> 1);
            ldsm_x4(af[mt], abase + rr * 128 + ((cc ^ (rr & 7)) << 4));
        }
        #pragma unroll
        for (int nt2 = 0; nt2 < 2; ++nt2) {
            int rr = wn * 32 + nt2 * 16 + (lane & 7) + ((grp >> 1) << 3);
            int cc = s * 2 + (grp & 1);
            uint32_t tmp[4];
            ldsm_x4(tmp, bbase + rr * 128 + ((cc ^ (rr & 7)) << 4));
            bf[nt2 * 2][0] = tmp[0]; bf[nt2 * 2][1] = tmp[1];
            bf[nt2 * 2 + 1][0] = tmp[2]; bf[nt2 * 2 + 1][1] = tmp[3];
        }
        #pragma unroll
        for (int mt = 0; mt < 4; ++mt)
            #pragma unroll
            for (int nt = 0; nt < 4; ++nt)
                mma16816(acc[mt][nt], af[mt], bf[nt]);
    }
}

__device__ __forceinline__ void gemm_core(const __nv_bfloat16* aHi, const __nv_bfloat16* aLo,
                                          const __nv_bfloat16* bHi, const __nv_bfloat16* bLo,
                                          char* smem) {
    const int tid = threadIdx.x;
    const int lane = tid & 31, wid = tid >> 5;
    const int wm = wid & 1, wn = wid >> 1;
    uint32_t sbase = smem_u32(smem);

    float acc[4][4][4];
    #pragma unroll
    for (int mt = 0; mt < 4; ++mt)
        #pragma unroll
        for (int nt = 0; nt < 4; ++nt)
            #pragma unroll
            for (int r = 0; r < 4; ++r) acc[mt][nt][r] = 0.f;

    issue_tile(sbase, 0, 0, tid, aHi, aLo, bHi, bLo);
    CP_COMMIT();
    int buf = 0;
    for (int c = 0; c < 24; ++c) {
        if (c + 1 < 24) {
            issue_tile(sbase, buf ^ 1, c + 1, tid, aHi, aLo, bHi, bLo);
            CP_COMMIT();
            CP_WAIT(1);
        } else {
            CP_WAIT(0);
        }
        __syncthreads();
        compute_tile(sbase, buf, lane, wm, wn, acc);
        __syncthreads();
        buf ^= 1;
    }

    float* sD = (float*)smem;
    #pragma unroll
    for (int mt = 0; mt < 4; ++mt)
        #pragma unroll
        for (int nt = 0; nt < 4; ++nt) {
            int r0 = wm * 64 + mt * 16 + (lane >> 2);
            int c0 = wn * 32 + nt * 8 + (lane & 3) * 2;
            sD[(c0    ) * 132 + r0    ] = acc[mt][nt][0];
            sD[(c0 + 1) * 132 + r0    ] = acc[mt][nt][1];
            sD[(c0    ) * 132 + r0 + 8] = acc[mt][nt][2];
            sD[(c0 + 1) * 132 + r0 + 8] = acc[mt][nt][3];
        }
    __syncthreads();
}

__global__ __launch_bounds__(256) void gemm1_kernel() {
    extern __shared__ char smem[];
    const int k0 = blockIdx.x * 128;
    const int n0 = blockIdx.y * 128;
    gemm_core(g_data_hi + (size_t)n0 * 512, g_data_lo + (size_t)n0 * 512,
              g_AT_hi + (size_t)k0 * 512, g_AT_lo + (size_t)k0 * 512, smem);
    const float* sD = (const float*)smem;
    const int tid = threadIdx.x;
    #pragma unroll
    for (int it = 0; it < 16; ++it) {
        int idx = tid + it * 256;
        int nn = idx >> 5, mm = (idx & 31) * 4;
        float4 v = *reinterpret_cast<const float4*>(sD + nn * 132 + mm);
        *reinterpret_cast<float4*>(&g_x[(size_t)(k0 + nn) * NROWS + n0 + mm]) = v;
    }
}

__global__ __launch_bounds__(256) void gemm2_kernel(const float* __restrict__ data,
                                                    float* __restrict__ out) {
    extern __shared__ char smem[];
    const int d0 = blockIdx.x * 128;
    const int n0 = blockIdx.y * 128;
    gemm_core(g_A_hi + (size_t)d0 * 512, g_A_lo + (size_t)d0 * 512,
              g_t_hi + (size_t)n0 * 512, g_t_lo + (size_t)n0 * 512, smem);
    const float* sD = (const float*)smem;
    const int tid = threadIdx.x;
    #pragma unroll
    for (int it = 0; it < 16; ++it) {
        int idx = tid + it * 256;
        int nn = idx >> 5, mm = (idx & 31) * 4;
        size_t gi = (size_t)(n0 + nn) * NDIMS + d0 + mm;
        float4 v = *reinterpret_cast<const float4*>(sD + nn * 132 + mm);
        float4 dv = *reinterpret_cast<const float4*>(data + gi);
        v.x += dv.x; v.y += dv.y; v.z += dv.z; v.w += dv.w;
        *reinterpret_cast<float4*>(out + gi) = v;
    }
}

// ---------------------------------------------------------------------------
// Spline v2 (LUT bracket): block = 8 k x 1024 n. Grid (64, 64).
// Reads g_x (K,N); writes t = y - x bf16 hi/lo to (N,K); partial logj sums.
// ---------------------------------------------------------------------------
__global__ __launch_bounds__(256) void spline_kernel(const float* __restrict__ xx,
                                                     const float* __restrict__ yy,
                                                     const float* __restrict__ delta) {
    __shared__ float sxx[8 * MKNOT], syy[8 * MKNOT], sdl[8 * MKNOT];
    __shared__ uint8_t slut[8 * LUTN];
    __shared__ __align__(16) __nv_bfloat16 sth[64 * 8], stl[64 * 8];
    __shared__ float sred[256];

    const int kg = blockIdx.x;          // 0..63
    const int ng = blockIdx.y;          // 0..63
    const int k0 = kg * 8;
    const int tid = threadIdx.x;

    for (int i = tid; i < 8 * MKNOT; i += 256) {
        int kl = i / MKNOT, m = i - kl * MKNOT;
        size_t gi = (size_t)(k0 + kl) * MKNOT + m;
        sxx[i] = xx[gi]; syy[i] = yy[gi]; sdl[i] = delta[gi];
    }
    for (int i = tid; i < (8 * LUTN) / 4; i += 256)
        reinterpret_cast<uint32_t*>(slut)[i] =
            reinterpret_cast<const uint32_t*>(g_lut + (size_t)k0 * LUTN)[i];
    __syncthreads();

    const int nl = tid & 63;
    const int kgrp = tid >> 6;

    for (int s = 0; s < 16; ++s) {
        const int n = ng * 1024 + s * 64 + nl;
        float acc = 0.f;
        #pragma unroll
        for (int r = 0; r < 2; ++r) {
            const int kl = r * 4 + kgrp;
            const float* kx = sxx + kl * MKNOT;
            const float* ky = syy + kl * MKNOT;
            const float* kd = sdl + kl * MKNOT;
            const float x = g_x[(size_t)(k0 + kl) * NROWS + n];

            // LUT bracket: at most one knot per cell -> one compare.
            int j = __float2int_rd((x + 4.0f) * LUT_SCALE);
            j = min(max(j, 0), LUTN - 1);
            int idx = (int)slut[kl * LUTN + j];
            if (idx < MKNOT && kx[idx] < x) ++idx;

            const bool below = (idx == 0);
            const bool above = (idx == MKNOT);
            const int b = min(max(idx, 1), MKNOT - 1) - 1;

            const float xk = kx[b], xk1 = kx[b + 1];
            const float yk = ky[b], yk1 = ky[b + 1];
            const float dk = kd[b], dk1 = kd[b + 1];
            const float dxk = xk1 - xk;
            const float dyk = yk1 - yk;
            const float sl = dyk / dxk;
            float xi = (x - xk) / dxk;
            xi = fminf(fmaxf(xi, 0.f), 1.f);
            const float xi1 = 1.f - xi;
            const float denom = sl + (dk1 + dk - 2.f * sl) * xi * xi1;
            float y = yk + dyk * (sl * xi * xi + dk * xi * xi1) / denom;
            const float num = dk1 * xi * xi + 2.f * sl * xi * xi1 + dk * xi1 * xi1;
            float logd = logf((sl * sl) * num / (denom * denom));
            if (below) { y = ky[0] + kd[0] * (x - kx[0]); logd = logf(kd[0]); }
            if (above) { y = ky[MKNOT - 1] + kd[MKNOT - 1] * (x - kx[MKNOT - 1]); logd = logf(kd[MKNOT - 1]); }

            const float t = y - x;
            acc += logd;
            __nv_bfloat16 h = __float2bfloat16(t);
            __nv_bfloat16 l = __float2bfloat16(t - __bfloat162float(h));
            sth[nl * 8 + kl] = h;
            stl[nl * 8 + kl] = l;
        }
        sred[tid] = acc;
        __syncthreads();

        if (tid < 64) {
            uint4 hv = *reinterpret_cast<const uint4*>(sth + tid * 8);
            *reinterpret_cast<uint4*>(g_t_hi + (size_t)(ng * 1024 + s * 64 + tid) * KDIM + k0) = hv;
        } else if (tid < 128) {
            int row = tid - 64;
            uint4 lv = *reinterpret_cast<const uint4*>(stl + row * 8);
            *reinterpret_cast<uint4*>(g_t_lo + (size_t)(ng * 1024 + s * 64 + row) * KDIM + k0) = lv;
        } else if (tid < 192) {
            int row = tid - 128;
            float p = sred[row] + sred[64 + row] + sred[128 + row] + sred[192 + row];
            g_partial[(size_t)kg * NROWS + ng * 1024 + s * 64 + row] = p;
        }
        __syncthreads();
    }
}

__global__ __launch_bounds__(256) void reduce_kernel(float* __restrict__ logj) {
    const int n = blockIdx.x * 256 + threadIdx.x;
    float s = 0.f;
    #pragma unroll
    for (int g = 0; g < 64; ++g) s += g_partial[(size_t)g * NROWS + n];
    logj[n] = s;
}

// ---------------------------------------------------------------------------
extern "C" void kernel_launch(void* const* d_in, const int* in_sizes, int n_in,
                              void* d_out, int out_size) {
    (void)in_sizes; (void)n_in; (void)out_size;
    const float* data  = (const float*)d_in[0];
    const float* A     = (const float*)d_in[1];
    const float* xx    = (const float*)d_in[2];
    const float* yy    = (const float*)d_in[3];
    const float* delta = (const float*)d_in[4];
    float* out  = (float*)d_out;
    float* logj = out + (size_t)NROWS * NDIMS;

    cudaFuncSetAttribute(gemm1_kernel, cudaFuncAttributeMaxDynamicSharedMemorySize, GEMM_SMEM);
    cudaFuncSetAttribute(gemm2_kernel, cudaFuncAttributeMaxDynamicSharedMemorySize, GEMM_SMEM);

    decomp_data_kernel<<<((size_t)NROWS * NDIMS) / 1024, 256>>>(data);
    decomp_A_kernel<<<(KDIM * NDIMS) / 256, 256>>>(A);
    lut_kernel<<<KDIM, 256>>>(xx);
    gemm1_kernel<<<dim3(4, NROWS / 128), 256, GEMM_SMEM>>>();
    spline_kernel<<<dim3(64, 64), 256>>>(xx, yy, delta);
    reduce_kernel<<<NROWS / 256, 256>>>(logj);
    gemm2_kernel<<<dim3(4, NROWS / 128), 256, GEMM_SMEM>>>(data, out);
}

// round 8
// speedup vs baseline: 2.5060x; 1.0730x over previous
#include <cuda_runtime.h>
#include <cuda_bf16.h>
#include <cstdint>

#define NROWS 65536
#define NDIMS 512
#define KDIM  512
#define MKNOT 200
#define LUTN  1024
#define LUT_SCALE (1024.0f / 12.0f)

// ---------------------------------------------------------------------------
// Device scratch (allocation-free)
// ---------------------------------------------------------------------------
__device__ __align__(16) float         g_x[(size_t)KDIM * NROWS];       // data0^T (K x N)
__device__ __align__(16) __nv_bfloat16 g_data_hi[(size_t)NROWS * NDIMS];
__device__ __align__(16) __nv_bfloat16 g_data_lo[(size_t)NROWS * NDIMS];
__device__ __align__(16) __nv_bfloat16 g_t_hi[(size_t)NROWS * KDIM];    // (N x K)
__device__ __align__(16) __nv_bfloat16 g_t_lo[(size_t)NROWS * KDIM];
__device__ __align__(16) __nv_bfloat16 g_A_hi[KDIM * NDIMS];            // [d][k]
__device__ __align__(16) __nv_bfloat16 g_A_lo[KDIM * NDIMS];
__device__ __align__(16) __nv_bfloat16 g_AT_hi[KDIM * NDIMS];           // [k][d]
__device__ __align__(16) __nv_bfloat16 g_AT_lo[KDIM * NDIMS];
__device__ __align__(16) float         g_partial[64 * NROWS];
__device__ __align__(16) uint8_t       g_lut[(size_t)KDIM * LUTN];

// ---------------------------------------------------------------------------
// PTX helpers (sm_80-level: legal on baseline compute_103 target)
// ---------------------------------------------------------------------------
__device__ __forceinline__ uint32_t smem_u32(const void* p) {
    uint32_t a;
    asm("{ .reg .u64 t; cvta.to.shared.u64 t, %1; cvt.u32.u64 %0, t; }" : "=r"(a) : "l"(p));
    return a;
}
#define CP_ASYNC16(dst, src) \
    asm volatile("cp.async.cg.shared.global [%0], [%1], 16;" :: "r"(dst), "l"(src))
#define CP_COMMIT() asm volatile("cp.async.commit_group;" ::: "memory")
#define CP_WAIT(n)  asm volatile("cp.async.wait_group %0;" :: "n"(n) : "memory")

__device__ __forceinline__ void ldsm_x4(uint32_t* r, uint32_t addr) {
    asm volatile("ldmatrix.sync.aligned.m8n8.x4.shared.b16 {%0,%1,%2,%3}, [%4];"
                 : "=r"(r[0]), "=r"(r[1]), "=r"(r[2]), "=r"(r[3]) : "r"(addr));
}
__device__ __forceinline__ void mma16816(float* d, const uint32_t* a, const uint32_t* b) {
    asm volatile(
        "mma.sync.aligned.m16n8k16.row.col.f32.bf16.bf16.f32 "
        "{%0,%1,%2,%3}, {%4,%5,%6,%7}, {%8,%9}, {%0,%1,%2,%3};"
        : "+f"(d[0]), "+f"(d[1]), "+f"(d[2]), "+f"(d[3])
        : "r"(a[0]), "r"(a[1]), "r"(a[2]), "r"(a[3]), "r"(b[0]), "r"(b[1]));
}

// ---------------------------------------------------------------------------
// Split decomposition
// ---------------------------------------------------------------------------
__global__ __launch_bounds__(256) void decomp_data_kernel(const float* __restrict__ data) {
    size_t i = ((size_t)blockIdx.x * 256 + threadIdx.x) * 4;
    float4 v = *reinterpret_cast<const float4*>(data + i);
    __nv_bfloat16 h0 = __float2bfloat16(v.x), h1 = __float2bfloat16(v.y);
    __nv_bfloat16 h2 = __float2bfloat16(v.z), h3 = __float2bfloat16(v.w);
    __nv_bfloat16 l0 = __float2bfloat16(v.x - __bfloat162float(h0));
    __nv_bfloat16 l1 = __float2bfloat16(v.y - __bfloat162float(h1));
    __nv_bfloat16 l2 = __float2bfloat16(v.z - __bfloat162float(h2));
    __nv_bfloat16 l3 = __float2bfloat16(v.w - __bfloat162float(h3));
    *reinterpret_cast<__nv_bfloat162*>(g_data_hi + i)     = __nv_bfloat162(h0, h1);
    *reinterpret_cast<__nv_bfloat162*>(g_data_hi + i + 2) = __nv_bfloat162(h2, h3);
    *reinterpret_cast<__nv_bfloat162*>(g_data_lo + i)     = __nv_bfloat162(l0, l1);
    *reinterpret_cast<__nv_bfloat162*>(g_data_lo + i + 2) = __nv_bfloat162(l2, l3);
}

__global__ __launch_bounds__(256) void decomp_A_kernel(const float* __restrict__ A) {
    int i = blockIdx.x * 256 + threadIdx.x;
    float v = A[i];
    __nv_bfloat16 h = __float2bfloat16(v);
    __nv_bfloat16 l = __float2bfloat16(v - __bfloat162float(h));
    g_A_hi[i] = h;
    g_A_lo[i] = l;
    int d = i >> 9, k = i & 511;
    g_AT_hi[k * 512 + d] = h;
    g_AT_lo[k * 512 + d] = l;
}

// ---------------------------------------------------------------------------
// LUT build: for each k, lut[j] = searchsorted_left(xx[k,:], -4 + j*12/1024).
// ---------------------------------------------------------------------------
__global__ __launch_bounds__(256) void lut_kernel(const float* __restrict__ xx) {
    __shared__ float sx[MKNOT];
    const int k = blockIdx.x;
    const int tid = threadIdx.x;
    if (tid < MKNOT) sx[tid] = xx[(size_t)k * MKNOT + tid];
    __syncthreads();
    for (int j = tid; j < LUTN; j += 256) {
        const float gx = -4.0f + (float)j * (12.0f / LUTN);
        int lo = 0, hi = MKNOT;
        while (lo < hi) {
            int mid = (lo + hi) >> 1;
            if (sx[mid] < gx) lo = mid + 1; else hi = mid;
        }
        g_lut[(size_t)k * LUTN + j] = (uint8_t)lo;
    }
}

// ---------------------------------------------------------------------------
// HMMA GEMM mainloop: D[128,128], K'=1536, 3 bf16 phases. Epilogue staged in
// 64-row halves so dynamic smem = 64KB exactly -> 2 CTAs/SM.
// ---------------------------------------------------------------------------
#define GEMM_SMEM 65536

__device__ __forceinline__ void issue_tile(uint32_t sbase, int buf, int c, int tid,
        const __nv_bfloat16* aHi, const __nv_bfloat16* aLo,
        const __nv_bfloat16* bHi, const __nv_bfloat16* bLo) {
    const int ph = c >> 3;
    const int koff = (c & 7) * 64;
    const __nv_bfloat16* a = (ph < 2) ? aHi : aLo;
    const __nv_bfloat16* b = (ph == 1) ? bLo : bHi;
    uint32_t abase = sbase + buf * 32768;
    uint32_t bbase = abase + 16384;
    #pragma unroll
    for (int it = 0; it < 4; ++it) {
        int i = tid + it * 256;
        int r = i >> 3, cc = i & 7;
        CP_ASYNC16(abase + r * 128 + ((cc ^ (r & 7)) << 4),
                   a + (size_t)r * 512 + koff + cc * 8);
    }
    #pragma unroll
    for (int it = 0; it < 4; ++it) {
        int i = tid + it * 256;
        int r = i >> 3, cc = i & 7;
        CP_ASYNC16(bbase + r * 128 + ((cc ^ (r & 7)) << 4),
                   b + (size_t)r * 512 + koff + cc * 8);
    }
}

__device__ __forceinline__ void compute_tile(uint32_t sbase, int buf, int lane,
                                             int wm, int wn, float acc[4][4][4]) {
    uint32_t abase = sbase + buf * 32768;
    uint32_t bbase = abase + 16384;
    const int grp = lane >> 3;
    #pragma unroll
    for (int s = 0; s < 4; ++s) {
        uint32_t af[4][4], bf[4][2];
        #pragma unroll
        for (int mt = 0; mt < 4; ++mt) {
            int rr = wm * 64 + mt * 16 + (lane & 7) + ((grp & 1) << 3);
            int cc = s * 2 + (grp >> 1);
            ldsm_x4(af[mt], abase + rr * 128 + ((cc ^ (rr & 7)) << 4));
        }
        #pragma unroll
        for (int nt2 = 0; nt2 < 2; ++nt2) {
            int rr = wn * 32 + nt2 * 16 + (lane & 7) + ((grp >> 1) << 3);
            int cc = s * 2 + (grp & 1);
            uint32_t tmp[4];
            ldsm_x4(tmp, bbase + rr * 128 + ((cc ^ (rr & 7)) << 4));
            bf[nt2 * 2][0] = tmp[0]; bf[nt2 * 2][1] = tmp[1];
            bf[nt2 * 2 + 1][0] = tmp[2]; bf[nt2 * 2 + 1][1] = tmp[3];
        }
        #pragma unroll
        for (int mt = 0; mt < 4; ++mt)
            #pragma unroll
            for (int nt = 0; nt < 4; ++nt)
                mma16816(acc[mt][nt], af[mt], bf[nt]);
    }
}

__device__ __forceinline__ void gemm_mainloop(const __nv_bfloat16* aHi, const __nv_bfloat16* aLo,
                                              const __nv_bfloat16* bHi, const __nv_bfloat16* bLo,
                                              uint32_t sbase, int tid, int lane, int wm, int wn,
                                              float acc[4][4][4]) {
    #pragma unroll
    for (int mt = 0; mt < 4; ++mt)
        #pragma unroll
        for (int nt = 0; nt < 4; ++nt)
            #pragma unroll
            for (int r = 0; r < 4; ++r) acc[mt][nt][r] = 0.f;

    issue_tile(sbase, 0, 0, tid, aHi, aLo, bHi, bLo);
    CP_COMMIT();
    int buf = 0;
    for (int c = 0; c < 24; ++c) {
        if (c + 1 < 24) {
            issue_tile(sbase, buf ^ 1, c + 1, tid, aHi, aLo, bHi, bLo);
            CP_COMMIT();
            CP_WAIT(1);
        } else {
            CP_WAIT(0);
        }
        __syncthreads();
        compute_tile(sbase, buf, lane, wm, wn, acc);
        __syncthreads();
        buf ^= 1;
    }
}

// Stage one 64-column half of D (columns c in [half*64, half*64+64)) into
// smem as sD[c - half*64][m] (stride 132), by the 4 warps owning that half.
__device__ __forceinline__ void stage_half(float* sD, const float acc[4][4][4],
                                           int wm, int wn, int lane, int half) {
    if ((wn >> 1) == half) {
        #pragma unroll
        for (int mt = 0; mt < 4; ++mt)
            #pragma unroll
            for (int nt = 0; nt < 4; ++nt) {
                int r0 = wm * 64 + mt * 16 + (lane >> 2);
                int c0 = (wn & 1) * 32 + nt * 8 + (lane & 3) * 2;
                sD[(c0    ) * 132 + r0    ] = acc[mt][nt][0];
                sD[(c0 + 1) * 132 + r0    ] = acc[mt][nt][1];
                sD[(c0    ) * 132 + r0 + 8] = acc[mt][nt][2];
                sD[(c0 + 1) * 132 + r0 + 8] = acc[mt][nt][3];
            }
    }
}

__global__ __launch_bounds__(256, 2) void gemm1_kernel() {
    extern __shared__ char smem[];
    const int k0 = blockIdx.x * 128;
    const int n0 = blockIdx.y * 128;
    const int tid = threadIdx.x;
    const int lane = tid & 31, wid = tid >> 5;
    const int wm = wid & 1, wn = wid >> 1;
    uint32_t sbase = smem_u32(smem);

    float acc[4][4][4];
    gemm_mainloop(g_data_hi + (size_t)n0 * 512, g_data_lo + (size_t)n0 * 512,
                  g_AT_hi + (size_t)k0 * 512, g_AT_lo + (size_t)k0 * 512,
                  sbase, tid, lane, wm, wn, acc);

    float* sD = (float*)smem;
    #pragma unroll
    for (int half = 0; half < 2; ++half) {
        stage_half(sD, acc, wm, wn, lane, half);
        __syncthreads();
        #pragma unroll
        for (int it = 0; it < 8; ++it) {
            int idx = tid + it * 256;
            int nn = idx >> 5, mm = (idx & 31) * 4;
            float4 v = *reinterpret_cast<const float4*>(sD + nn * 132 + mm);
            *reinterpret_cast<float4*>(&g_x[(size_t)(k0 + half * 64 + nn) * NROWS + n0 + mm]) = v;
        }
        __syncthreads();
    }
}

__global__ __launch_bounds__(256, 2) void gemm2_kernel(const float* __restrict__ data,
                                                       float* __restrict__ out) {
    extern __shared__ char smem[];
    const int d0 = blockIdx.x * 128;
    const int n0 = blockIdx.y * 128;
    const int tid = threadIdx.x;
    const int lane = tid & 31, wid = tid >> 5;
    const int wm = wid & 1, wn = wid >> 1;
    uint32_t sbase = smem_u32(smem);

    float acc[4][4][4];
    gemm_mainloop(g_A_hi + (size_t)d0 * 512, g_A_lo + (size_t)d0 * 512,
                  g_t_hi + (size_t)n0 * 512, g_t_lo + (size_t)n0 * 512,
                  sbase, tid, lane, wm, wn, acc);

    float* sD = (float*)smem;
    #pragma unroll
    for (int half = 0; half < 2; ++half) {
        stage_half(sD, acc, wm, wn, lane, half);
        __syncthreads();
        #pragma unroll
        for (int it = 0; it < 8; ++it) {
            int idx = tid + it * 256;
            int nn = idx >> 5, mm = (idx & 31) * 4;
            size_t gi = (size_t)(n0 + half * 64 + nn) * NDIMS + d0 + mm;
            float4 v = *reinterpret_cast<const float4*>(sD + nn * 132 + mm);
            float4 dv = *reinterpret_cast<const float4*>(data + gi);
            v.x += dv.x; v.y += dv.y; v.z += dv.z; v.w += dv.w;
            *reinterpret_cast<float4*>(out + gi) = v;
        }
        __syncthreads();
    }
}

// ---------------------------------------------------------------------------
// Spline (LUT bracket): block = 8 k x 1024 n. Grid (64, 64).
// ---------------------------------------------------------------------------
__global__ __launch_bounds__(256) void spline_kernel(const float* __restrict__ xx,
                                                     const float* __restrict__ yy,
                                                     const float* __restrict__ delta) {
    __shared__ float sxx[8 * MKNOT], syy[8 * MKNOT], sdl[8 * MKNOT];
    __shared__ uint8_t slut[8 * LUTN];
    __shared__ __align__(16) __nv_bfloat16 sth[64 * 8], stl[64 * 8];
    __shared__ float sred[256];

    const int kg = blockIdx.x;
    const int ng = blockIdx.y;
    const int k0 = kg * 8;
    const int tid = threadIdx.x;

    for (int i = tid; i < 8 * MKNOT; i += 256) {
        int kl = i / MKNOT, m = i - kl * MKNOT;
        size_t gi = (size_t)(k0 + kl) * MKNOT + m;
        sxx[i] = xx[gi]; syy[i] = yy[gi]; sdl[i] = delta[gi];
    }
    for (int i = tid; i < (8 * LUTN) / 4; i += 256)
        reinterpret_cast<uint32_t*>(slut)[i] =
            reinterpret_cast<const uint32_t*>(g_lut + (size_t)k0 * LUTN)[i];
    __syncthreads();

    const int nl = tid & 63;
    const int kgrp = tid >> 6;

    for (int s = 0; s < 16; ++s) {
        const int n = ng * 1024 + s * 64 + nl;
        float acc = 0.f;
        #pragma unroll
        for (int r = 0; r < 2; ++r) {
            const int kl = r * 4 + kgrp;
            const float* kx = sxx + kl * MKNOT;
            const float* ky = syy + kl * MKNOT;
            const float* kd = sdl + kl * MKNOT;
            const float x = g_x[(size_t)(k0 + kl) * NROWS + n];

            int j = __float2int_rd((x + 4.0f) * LUT_SCALE);
            j = min(max(j, 0), LUTN - 1);
            int idx = (int)slut[kl * LUTN + j];
            if (idx < MKNOT && kx[idx] < x) ++idx;

            const bool below = (idx == 0);
            const bool above = (idx == MKNOT);
            const int b = min(max(idx, 1), MKNOT - 1) - 1;

            const float xk = kx[b], xk1 = kx[b + 1];
            const float yk = ky[b], yk1 = ky[b + 1];
            const float dk = kd[b], dk1 = kd[b + 1];
            const float dxk = xk1 - xk;
            const float dyk = yk1 - yk;
            const float sl = dyk / dxk;
            float xi = (x - xk) / dxk;
            xi = fminf(fmaxf(xi, 0.f), 1.f);
            const float xi1 = 1.f - xi;
            const float denom = sl + (dk1 + dk - 2.f * sl) * xi * xi1;
            float y = yk + dyk * (sl * xi * xi + dk * xi * xi1) / denom;
            const float num = dk1 * xi * xi + 2.f * sl * xi * xi1 + dk * xi1 * xi1;
            float logd = logf((sl * sl) * num / (denom * denom));
            if (below) { y = ky[0] + kd[0] * (x - kx[0]); logd = logf(kd[0]); }
            if (above) { y = ky[MKNOT - 1] + kd[MKNOT - 1] * (x - kx[MKNOT - 1]); logd = logf(kd[MKNOT - 1]); }

            const float t = y - x;
            acc += logd;
            __nv_bfloat16 h = __float2bfloat16(t);
            __nv_bfloat16 l = __float2bfloat16(t - __bfloat162float(h));
            sth[nl * 8 + kl] = h;
            stl[nl * 8 + kl] = l;
        }
        sred[tid] = acc;
        __syncthreads();

        if (tid < 64) {
            uint4 hv = *reinterpret_cast<const uint4*>(sth + tid * 8);
            *reinterpret_cast<uint4*>(g_t_hi + (size_t)(ng * 1024 + s * 64 + tid) * KDIM + k0) = hv;
        } else if (tid < 128) {
            int row = tid - 64;
            uint4 lv = *reinterpret_cast<const uint4*>(stl + row * 8);
            *reinterpret_cast<uint4*>(g_t_lo + (size_t)(ng * 1024 + s * 64 + row) * KDIM + k0) = lv;
        } else if (tid < 192) {
            int row = tid - 128;
            float p = sred[row] + sred[64 + row] + sred[128 + row] + sred[192 + row];
            g_partial[(size_t)kg * NROWS + ng * 1024 + s * 64 + row] = p;
        }
        __syncthreads();
    }
}

__global__ __launch_bounds__(256) void reduce_kernel(float* __restrict__ logj) {
    const int n = blockIdx.x * 256 + threadIdx.x;
    float s = 0.f;
    #pragma unroll
    for (int g = 0; g < 64; ++g) s += g_partial[(size_t)g * NROWS + n];
    logj[n] = s;
}

// ---------------------------------------------------------------------------
extern "C" void kernel_launch(void* const* d_in, const int* in_sizes, int n_in,
                              void* d_out, int out_size) {
    (void)in_sizes; (void)n_in; (void)out_size;
    const float* data  = (const float*)d_in[0];
    const float* A     = (const float*)d_in[1];
    const float* xx    = (const float*)d_in[2];
    const float* yy    = (const float*)d_in[3];
    const float* delta = (const float*)d_in[4];
    float* out  = (float*)d_out;
    float* logj = out + (size_t)NROWS * NDIMS;

    cudaFuncSetAttribute(gemm1_kernel, cudaFuncAttributeMaxDynamicSharedMemorySize, GEMM_SMEM);
    cudaFuncSetAttribute(gemm2_kernel, cudaFuncAttributeMaxDynamicSharedMemorySize, GEMM_SMEM);
    cudaFuncSetAttribute(gemm1_kernel, cudaFuncAttributePreferredSharedMemoryCarveout,
                         cudaSharedmemCarveoutMaxShared);
    cudaFuncSetAttribute(gemm2_kernel, cudaFuncAttributePreferredSharedMemoryCarveout,
                         cudaSharedmemCarveoutMaxShared);

    decomp_data_kernel<<<((size_t)NROWS * NDIMS) / 1024, 256>>>(data);
    decomp_A_kernel<<<(KDIM * NDIMS) / 256, 256>>>(A);
    lut_kernel<<<KDIM, 256>>>(xx);
    gemm1_kernel<<<dim3(4, NROWS / 128), 256, GEMM_SMEM>>>();
    spline_kernel<<<dim3(64, 64), 256>>>(xx, yy, delta);
    reduce_kernel<<<NROWS / 256, 256>>>(logj);
    gemm2_kernel<<<dim3(4, NROWS / 128), 256, GEMM_SMEM>>>(data, out);
}

// round 9
// speedup vs baseline: 2.5246x; 1.0074x over previous
#include <cuda_runtime.h>
#include <cuda_bf16.h>
#include <cstdint>

#define NROWS 65536
#define NDIMS 512
#define KDIM  512
#define MKNOT 200
#define LUTN  1024
#define LUT_SCALE (1024.0f / 12.0f)

// ---------------------------------------------------------------------------
// Device scratch (allocation-free)
// ---------------------------------------------------------------------------
__device__ __align__(16) float         g_x[(size_t)KDIM * NROWS];       // data0^T (K x N)
__device__ __align__(16) __nv_bfloat16 g_data_hi[(size_t)NROWS * NDIMS];
__device__ __align__(16) __nv_bfloat16 g_data_lo[(size_t)NROWS * NDIMS];
__device__ __align__(16) __nv_bfloat16 g_t_hi[(size_t)NROWS * KDIM];    // (N x K)
__device__ __align__(16) __nv_bfloat16 g_t_lo[(size_t)NROWS * KDIM];
__device__ __align__(16) __nv_bfloat16 g_A_hi[KDIM * NDIMS];            // [d][k]
__device__ __align__(16) __nv_bfloat16 g_A_lo[KDIM * NDIMS];
__device__ __align__(16) __nv_bfloat16 g_AT_hi[KDIM * NDIMS];           // [k][d]
__device__ __align__(16) __nv_bfloat16 g_AT_lo[KDIM * NDIMS];
__device__ __align__(16) float         g_partial[64 * NROWS];
__device__ __align__(16) uint8_t       g_lut[(size_t)KDIM * LUTN];

// ---------------------------------------------------------------------------
// PTX helpers (sm_80-level: legal on baseline compute_103 target)
// ---------------------------------------------------------------------------
__device__ __forceinline__ uint32_t smem_u32(const void* p) {
    uint32_t a;
    asm("{ .reg .u64 t; cvta.to.shared.u64 t, %1; cvt.u32.u64 %0, t; }" : "=r"(a) : "l"(p));
    return a;
}
#define CP_ASYNC16(dst, src) \
    asm volatile("cp.async.cg.shared.global [%0], [%1], 16;" :: "r"(dst), "l"(src))
#define CP_COMMIT() asm volatile("cp.async.commit_group;" ::: "memory")
#define CP_WAIT(n)  asm volatile("cp.async.wait_group %0;" :: "n"(n) : "memory")

__device__ __forceinline__ void ldsm_x4(uint32_t* r, uint32_t addr) {
    asm volatile("ldmatrix.sync.aligned.m8n8.x4.shared.b16 {%0,%1,%2,%3}, [%4];"
                 : "=r"(r[0]), "=r"(r[1]), "=r"(r[2]), "=r"(r[3]) : "r"(addr));
}
__device__ __forceinline__ void mma16816(float* d, const uint32_t* a, const uint32_t* b) {
    asm volatile(
        "mma.sync.aligned.m16n8k16.row.col.f32.bf16.bf16.f32 "
        "{%0,%1,%2,%3}, {%4,%5,%6,%7}, {%8,%9}, {%0,%1,%2,%3};"
        : "+f"(d[0]), "+f"(d[1]), "+f"(d[2]), "+f"(d[3])
        : "r"(a[0]), "r"(a[1]), "r"(a[2]), "r"(a[3]), "r"(b[0]), "r"(b[1]));
}

// ---------------------------------------------------------------------------
// Split decomposition
// ---------------------------------------------------------------------------
__global__ __launch_bounds__(256) void decomp_data_kernel(const float* __restrict__ data) {
    size_t i = ((size_t)blockIdx.x * 256 + threadIdx.x) * 4;
    float4 v = *reinterpret_cast<const float4*>(data + i);
    __nv_bfloat16 h0 = __float2bfloat16(v.x), h1 = __float2bfloat16(v.y);
    __nv_bfloat16 h2 = __float2bfloat16(v.z), h3 = __float2bfloat16(v.w);
    __nv_bfloat16 l0 = __float2bfloat16(v.x - __bfloat162float(h0));
    __nv_bfloat16 l1 = __float2bfloat16(v.y - __bfloat162float(h1));
    __nv_bfloat16 l2 = __float2bfloat16(v.z - __bfloat162float(h2));
    __nv_bfloat16 l3 = __float2bfloat16(v.w - __bfloat162float(h3));
    *reinterpret_cast<__nv_bfloat162*>(g_data_hi + i)     = __nv_bfloat162(h0, h1);
    *reinterpret_cast<__nv_bfloat162*>(g_data_hi + i + 2) = __nv_bfloat162(h2, h3);
    *reinterpret_cast<__nv_bfloat162*>(g_data_lo + i)     = __nv_bfloat162(l0, l1);
    *reinterpret_cast<__nv_bfloat162*>(g_data_lo + i + 2) = __nv_bfloat162(l2, l3);
}

__global__ __launch_bounds__(256) void decomp_A_kernel(const float* __restrict__ A) {
    int i = blockIdx.x * 256 + threadIdx.x;
    float v = A[i];
    __nv_bfloat16 h = __float2bfloat16(v);
    __nv_bfloat16 l = __float2bfloat16(v - __bfloat162float(h));
    g_A_hi[i] = h;
    g_A_lo[i] = l;
    int d = i >> 9, k = i & 511;
    g_AT_hi[k * 512 + d] = h;
    g_AT_lo[k * 512 + d] = l;
}

// ---------------------------------------------------------------------------
// LUT build: for each k, lut[j] = searchsorted_left(xx[k,:], -4 + j*12/1024).
// ---------------------------------------------------------------------------
__global__ __launch_bounds__(256) void lut_kernel(const float* __restrict__ xx) {
    __shared__ float sx[MKNOT];
    const int k = blockIdx.x;
    const int tid = threadIdx.x;
    if (tid < MKNOT) sx[tid] = xx[(size_t)k * MKNOT + tid];
    __syncthreads();
    for (int j = tid; j < LUTN; j += 256) {
        const float gx = -4.0f + (float)j * (12.0f / LUTN);
        int lo = 0, hi = MKNOT;
        while (lo < hi) {
            int mid = (lo + hi) >> 1;
            if (sx[mid] < gx) lo = mid + 1; else hi = mid;
        }
        g_lut[(size_t)k * LUTN + j] = (uint8_t)lo;
    }
}

// ---------------------------------------------------------------------------
// HMMA GEMM mainloop: D[128,128], K'=1536 (24 chunks of 64), 3 bf16 phases.
// 3-stage cp.async pipeline, ONE __syncthreads per chunk.
// smem: 3 x 32KB operand buffers = 96KB; epilogue reuses first 33.8KB.
// ---------------------------------------------------------------------------
#define GEMM_SMEM (3 * 32768)

__device__ __forceinline__ void issue_tile(uint32_t sbase, int buf, int c, int tid,
        const __nv_bfloat16* aHi, const __nv_bfloat16* aLo,
        const __nv_bfloat16* bHi, const __nv_bfloat16* bLo) {
    const int ph = c >> 3;
    const int koff = (c & 7) * 64;
    const __nv_bfloat16* a = (ph < 2) ? aHi : aLo;
    const __nv_bfloat16* b = (ph == 1) ? bLo : bHi;
    uint32_t abase = sbase + buf * 32768;
    uint32_t bbase = abase + 16384;
    #pragma unroll
    for (int it = 0; it < 4; ++it) {
        int i = tid + it * 256;
        int r = i >> 3, cc = i & 7;
        CP_ASYNC16(abase + r * 128 + ((cc ^ (r & 7)) << 4),
                   a + (size_t)r * 512 + koff + cc * 8);
    }
    #pragma unroll
    for (int it = 0; it < 4; ++it) {
        int i = tid + it * 256;
        int r = i >> 3, cc = i & 7;
        CP_ASYNC16(bbase + r * 128 + ((cc ^ (r & 7)) << 4),
                   b + (size_t)r * 512 + koff + cc * 8);
    }
}

__device__ __forceinline__ void compute_tile(uint32_t sbase, int buf, int lane,
                                             int wm, int wn, float acc[4][4][4]) {
    uint32_t abase = sbase + buf * 32768;
    uint32_t bbase = abase + 16384;
    const int grp = lane >> 3;
    #pragma unroll
    for (int s = 0; s < 4; ++s) {
        uint32_t af[4][4], bf[4][2];
        #pragma unroll
        for (int mt = 0; mt < 4; ++mt) {
            int rr = wm * 64 + mt * 16 + (lane & 7) + ((grp & 1) << 3);
            int cc = s * 2 + (grp >> 1);
            ldsm_x4(af[mt], abase + rr * 128 + ((cc ^ (rr & 7)) << 4));
        }
        #pragma unroll
        for (int nt2 = 0; nt2 < 2; ++nt2) {
            int rr = wn * 32 + nt2 * 16 + (lane & 7) + ((grp >> 1) << 3);
            int cc = s * 2 + (grp & 1);
            uint32_t tmp[4];
            ldsm_x4(tmp, bbase + rr * 128 + ((cc ^ (rr & 7)) << 4));
            bf[nt2 * 2][0] = tmp[0]; bf[nt2 * 2][1] = tmp[1];
            bf[nt2 * 2 + 1][0] = tmp[2]; bf[nt2 * 2 + 1][1] = tmp[3];
        }
        #pragma unroll
        for (int mt = 0; mt < 4; ++mt)
            #pragma unroll
            for (int nt = 0; nt < 4; ++nt)
                mma16816(acc[mt][nt], af[mt], bf[nt]);
    }
}

__device__ __forceinline__ void gemm_mainloop(const __nv_bfloat16* aHi, const __nv_bfloat16* aLo,
                                              const __nv_bfloat16* bHi, const __nv_bfloat16* bLo,
                                              uint32_t sbase, int tid, int lane, int wm, int wn,
                                              float acc[4][4][4]) {
    #pragma unroll
    for (int mt = 0; mt < 4; ++mt)
        #pragma unroll
        for (int nt = 0; nt < 4; ++nt)
            #pragma unroll
            for (int r = 0; r < 4; ++r) acc[mt][nt][r] = 0.f;

    issue_tile(sbase, 0, 0, tid, aHi, aLo, bHi, bLo);
    CP_COMMIT();
    issue_tile(sbase, 1, 1, tid, aHi, aLo, bHi, bLo);
    CP_COMMIT();

    int buf = 0, nxt = 2;
    for (int c = 0; c < 24; ++c) {
        if (c == 23) { CP_WAIT(0); } else { CP_WAIT(1); }
        __syncthreads();
        // Issue chunk c+2 into buffer (c+2)%3 = buffer freed by compute(c-1),
        // which all warps completed before this barrier.
        if (c + 2 < 24) {
            issue_tile(sbase, nxt, c + 2, tid, aHi, aLo, bHi, bLo);
            CP_COMMIT();
        }
        compute_tile(sbase, buf, lane, wm, wn, acc);
        buf = (buf == 2) ? 0 : buf + 1;
        nxt = (nxt == 2) ? 0 : nxt + 1;
    }
    __syncthreads();   // all compute done before epilogue reuses smem
}

// Stage one 64-column half of D (columns c in [half*64, half*64+64)) into
// smem as sD[c - half*64][m] (stride 132), by the 4 warps owning that half.
__device__ __forceinline__ void stage_half(float* sD, const float acc[4][4][4],
                                           int wm, int wn, int lane, int half) {
    if ((wn >> 1) == half) {
        #pragma unroll
        for (int mt = 0; mt < 4; ++mt)
            #pragma unroll
            for (int nt = 0; nt < 4; ++nt) {
                int r0 = wm * 64 + mt * 16 + (lane >> 2);
                int c0 = (wn & 1) * 32 + nt * 8 + (lane & 3) * 2;
                sD[(c0    ) * 132 + r0    ] = acc[mt][nt][0];
                sD[(c0 + 1) * 132 + r0    ] = acc[mt][nt][1];
                sD[(c0    ) * 132 + r0 + 8] = acc[mt][nt][2];
                sD[(c0 + 1) * 132 + r0 + 8] = acc[mt][nt][3];
            }
    }
}

__global__ __launch_bounds__(256, 2) void gemm1_kernel() {
    extern __shared__ char smem[];
    const int k0 = blockIdx.x * 128;
    const int n0 = blockIdx.y * 128;
    const int tid = threadIdx.x;
    const int lane = tid & 31, wid = tid >> 5;
    const int wm = wid & 1, wn = wid >> 1;
    uint32_t sbase = smem_u32(smem);

    float acc[4][4][4];
    gemm_mainloop(g_data_hi + (size_t)n0 * 512, g_data_lo + (size_t)n0 * 512,
                  g_AT_hi + (size_t)k0 * 512, g_AT_lo + (size_t)k0 * 512,
                  sbase, tid, lane, wm, wn, acc);

    float* sD = (float*)smem;
    #pragma unroll
    for (int half = 0; half < 2; ++half) {
        stage_half(sD, acc, wm, wn, lane, half);
        __syncthreads();
        #pragma unroll
        for (int it = 0; it < 8; ++it) {
            int idx = tid + it * 256;
            int nn = idx >> 5, mm = (idx & 31) * 4;
            float4 v = *reinterpret_cast<const float4*>(sD + nn * 132 + mm);
            *reinterpret_cast<float4*>(&g_x[(size_t)(k0 + half * 64 + nn) * NROWS + n0 + mm]) = v;
        }
        __syncthreads();
    }
}

__global__ __launch_bounds__(256, 2) void gemm2_kernel(const float* __restrict__ data,
                                                       float* __restrict__ out) {
    extern __shared__ char smem[];
    const int d0 = blockIdx.x * 128;
    const int n0 = blockIdx.y * 128;
    const int tid = threadIdx.x;
    const int lane = tid & 31, wid = tid >> 5;
    const int wm = wid & 1, wn = wid >> 1;
    uint32_t sbase = smem_u32(smem);

    float acc[4][4][4];
    gemm_mainloop(g_A_hi + (size_t)d0 * 512, g_A_lo + (size_t)d0 * 512,
                  g_t_hi + (size_t)n0 * 512, g_t_lo + (size_t)n0 * 512,
                  sbase, tid, lane, wm, wn, acc);

    float* sD = (float*)smem;
    #pragma unroll
    for (int half = 0; half < 2; ++half) {
        stage_half(sD, acc, wm, wn, lane, half);
        __syncthreads();
        #pragma unroll
        for (int it = 0; it < 8; ++it) {
            int idx = tid + it * 256;
            int nn = idx >> 5, mm = (idx & 31) * 4;
            size_t gi = (size_t)(n0 + half * 64 + nn) * NDIMS + d0 + mm;
            float4 v = *reinterpret_cast<const float4*>(sD + nn * 132 + mm);
            float4 dv = *reinterpret_cast<const float4*>(data + gi);
            v.x += dv.x; v.y += dv.y; v.z += dv.z; v.w += dv.w;
            *reinterpret_cast<float4*>(out + gi) = v;
        }
        __syncthreads();
    }
}

// ---------------------------------------------------------------------------
// Spline (LUT bracket): block = 8 k x 1024 n. Grid (64, 64).
// ---------------------------------------------------------------------------
__global__ __launch_bounds__(256) void spline_kernel(const float* __restrict__ xx,
                                                     const float* __restrict__ yy,
                                                     const float* __restrict__ delta) {
    __shared__ float sxx[8 * MKNOT], syy[8 * MKNOT], sdl[8 * MKNOT];
    __shared__ uint8_t slut[8 * LUTN];
    __shared__ __align__(16) __nv_bfloat16 sth[64 * 8], stl[64 * 8];
    __shared__ float sred[256];

    const int kg = blockIdx.x;
    const int ng = blockIdx.y;
    const int k0 = kg * 8;
    const int tid = threadIdx.x;

    for (int i = tid; i < 8 * MKNOT; i += 256) {
        int kl = i / MKNOT, m = i - kl * MKNOT;
        size_t gi = (size_t)(k0 + kl) * MKNOT + m;
        sxx[i] = xx[gi]; syy[i] = yy[gi]; sdl[i] = delta[gi];
    }
    for (int i = tid; i < (8 * LUTN) / 4; i += 256)
        reinterpret_cast<uint32_t*>(slut)[i] =
            reinterpret_cast<const uint32_t*>(g_lut + (size_t)k0 * LUTN)[i];
    __syncthreads();

    const int nl = tid & 63;
    const int kgrp = tid >> 6;

    for (int s = 0; s < 16; ++s) {
        const int n = ng * 1024 + s * 64 + nl;
        float acc = 0.f;
        #pragma unroll
        for (int r = 0; r < 2; ++r) {
            const int kl = r * 4 + kgrp;
            const float* kx = sxx + kl * MKNOT;
            const float* ky = syy + kl * MKNOT;
            const float* kd = sdl + kl * MKNOT;
            const float x = g_x[(size_t)(k0 + kl) * NROWS + n];

            int j = __float2int_rd((x + 4.0f) * LUT_SCALE);
            j = min(max(j, 0), LUTN - 1);
            int idx = (int)slut[kl * LUTN + j];
            if (idx < MKNOT && kx[idx] < x) ++idx;

            const bool below = (idx == 0);
            const bool above = (idx == MKNOT);
            const int b = min(max(idx, 1), MKNOT - 1) - 1;

            const float xk = kx[b], xk1 = kx[b + 1];
            const float yk = ky[b], yk1 = ky[b + 1];
            const float dk = kd[b], dk1 = kd[b + 1];
            const float dxk = xk1 - xk;
            const float dyk = yk1 - yk;
            const float sl = dyk / dxk;
            float xi = (x - xk) / dxk;
            xi = fminf(fmaxf(xi, 0.f), 1.f);
            const float xi1 = 1.f - xi;
            const float denom = sl + (dk1 + dk - 2.f * sl) * xi * xi1;
            float y = yk + dyk * (sl * xi * xi + dk * xi * xi1) / denom;
            const float num = dk1 * xi * xi + 2.f * sl * xi * xi1 + dk * xi1 * xi1;
            float logd = logf((sl * sl) * num / (denom * denom));
            if (below) { y = ky[0] + kd[0] * (x - kx[0]); logd = logf(kd[0]); }
            if (above) { y = ky[MKNOT - 1] + kd[MKNOT - 1] * (x - kx[MKNOT - 1]); logd = logf(kd[MKNOT - 1]); }

            const float t = y - x;
            acc += logd;
            __nv_bfloat16 h = __float2bfloat16(t);
            __nv_bfloat16 l = __float2bfloat16(t - __bfloat162float(h));
            sth[nl * 8 + kl] = h;
            stl[nl * 8 + kl] = l;
        }
        sred[tid] = acc;
        __syncthreads();

        if (tid < 64) {
            uint4 hv = *reinterpret_cast<const uint4*>(sth + tid * 8);
            *reinterpret_cast<uint4*>(g_t_hi + (size_t)(ng * 1024 + s * 64 + tid) * KDIM + k0) = hv;
        } else if (tid < 128) {
            int row = tid - 64;
            uint4 lv = *reinterpret_cast<const uint4*>(stl + row * 8);
            *reinterpret_cast<uint4*>(g_t_lo + (size_t)(ng * 1024 + s * 64 + row) * KDIM + k0) = lv;
        } else if (tid < 192) {
            int row = tid - 128;
            float p = sred[row] + sred[64 + row] + sred[128 + row] + sred[192 + row];
            g_partial[(size_t)kg * NROWS + ng * 1024 + s * 64 + row] = p;
        }
        __syncthreads();
    }
}

__global__ __launch_bounds__(256) void reduce_kernel(float* __restrict__ logj) {
    const int n = blockIdx.x * 256 + threadIdx.x;
    float s = 0.f;
    #pragma unroll
    for (int g = 0; g < 64; ++g) s += g_partial[(size_t)g * NROWS + n];
    logj[n] = s;
}

// ---------------------------------------------------------------------------
extern "C" void kernel_launch(void* const* d_in, const int* in_sizes, int n_in,
                              void* d_out, int out_size) {
    (void)in_sizes; (void)n_in; (void)out_size;
    const float* data  = (const float*)d_in[0];
    const float* A     = (const float*)d_in[1];
    const float* xx    = (const float*)d_in[2];
    const float* yy    = (const float*)d_in[3];
    const float* delta = (const float*)d_in[4];
    float* out  = (float*)d_out;
    float* logj = out + (size_t)NROWS * NDIMS;

    cudaFuncSetAttribute(gemm1_kernel, cudaFuncAttributeMaxDynamicSharedMemorySize, GEMM_SMEM);
    cudaFuncSetAttribute(gemm2_kernel, cudaFuncAttributeMaxDynamicSharedMemorySize, GEMM_SMEM);
    cudaFuncSetAttribute(gemm1_kernel, cudaFuncAttributePreferredSharedMemoryCarveout,
                         cudaSharedmemCarveoutMaxShared);
    cudaFuncSetAttribute(gemm2_kernel, cudaFuncAttributePreferredSharedMemoryCarveout,
                         cudaSharedmemCarveoutMaxShared);

    decomp_data_kernel<<<((size_t)NROWS * NDIMS) / 1024, 256>>>(data);
    decomp_A_kernel<<<(KDIM * NDIMS) / 256, 256>>>(A);
    lut_kernel<<<KDIM, 256>>>(xx);
    gemm1_kernel<<<dim3(4, NROWS / 128), 256, GEMM_SMEM>>>();
    spline_kernel<<<dim3(64, 64), 256>>>(xx, yy, delta);
    reduce_kernel<<<NROWS / 256, 256>>>(logj);
    gemm2_kernel<<<dim3(4, NROWS / 128), 256, GEMM_SMEM>>>(data, out);
}

// round 11
// speedup vs baseline: 2.5821x; 1.0228x over previous
#include <cuda_runtime.h>
#include <cuda_bf16.h>
#include <cstdint>

#define NROWS 65536
#define NDIMS 512
#define KDIM  512
#define MKNOT 200
#define LUTN  1024
#define LUT_SCALE (1024.0f / 12.0f)

// ---------------------------------------------------------------------------
// Device scratch (allocation-free)
// ---------------------------------------------------------------------------
__device__ __align__(16) float         g_x[(size_t)KDIM * NROWS];       // data0^T (K x N)
__device__ __align__(16) __nv_bfloat16 g_data_hi[(size_t)NROWS * NDIMS];
__device__ __align__(16) __nv_bfloat16 g_data_lo[(size_t)NROWS * NDIMS];
__device__ __align__(16) __nv_bfloat16 g_t_hi[(size_t)NROWS * KDIM];    // (N x K)
__device__ __align__(16) __nv_bfloat16 g_t_lo[(size_t)NROWS * KDIM];
__device__ __align__(16) __nv_bfloat16 g_A_hi[KDIM * NDIMS];            // [d][k]
__device__ __align__(16) __nv_bfloat16 g_A_lo[KDIM * NDIMS];
__device__ __align__(16) __nv_bfloat16 g_AT_hi[KDIM * NDIMS];           // [k][d]
__device__ __align__(16) __nv_bfloat16 g_AT_lo[KDIM * NDIMS];
__device__ __align__(16) float         g_partial[64 * NROWS];
__device__ __align__(16) uint8_t       g_lut[(size_t)KDIM * LUTN];

// ---------------------------------------------------------------------------
// PTX helpers (sm_80-level: legal on baseline compute_103 target)
// ---------------------------------------------------------------------------
__device__ __forceinline__ uint32_t smem_u32(const void* p) {
    uint32_t a;
    asm("{ .reg .u64 t; cvta.to.shared.u64 t, %1; cvt.u32.u64 %0, t; }" : "=r"(a) : "l"(p));
    return a;
}
#define CP_ASYNC16(dst, src) \
    asm volatile("cp.async.cg.shared.global [%0], [%1], 16;" :: "r"(dst), "l"(src))
#define CP_COMMIT() asm volatile("cp.async.commit_group;" ::: "memory")
#define CP_WAIT(n)  asm volatile("cp.async.wait_group %0;" :: "n"(n) : "memory")

__device__ __forceinline__ void ldsm_x4(uint32_t* r, uint32_t addr) {
    asm volatile("ldmatrix.sync.aligned.m8n8.x4.shared.b16 {%0,%1,%2,%3}, [%4];"
                 : "=r"(r[0]), "=r"(r[1]), "=r"(r[2]), "=r"(r[3]) : "r"(addr));
}
__device__ __forceinline__ void mma16816(float* d, const uint32_t* a, const uint32_t* b) {
    asm volatile(
        "mma.sync.aligned.m16n8k16.row.col.f32.bf16.bf16.f32 "
        "{%0,%1,%2,%3}, {%4,%5,%6,%7}, {%8,%9}, {%0,%1,%2,%3};"
        : "+f"(d[0]), "+f"(d[1]), "+f"(d[2]), "+f"(d[3])
        : "r"(a[0]), "r"(a[1]), "r"(a[2]), "r"(a[3]), "r"(b[0]), "r"(b[1]));
}

// ---------------------------------------------------------------------------
// Split decomposition
// ---------------------------------------------------------------------------
__global__ __launch_bounds__(256) void decomp_data_kernel(const float* __restrict__ data) {
    size_t i = ((size_t)blockIdx.x * 256 + threadIdx.x) * 4;
    float4 v = *reinterpret_cast<const float4*>(data + i);
    __nv_bfloat16 h0 = __float2bfloat16(v.x), h1 = __float2bfloat16(v.y);
    __nv_bfloat16 h2 = __float2bfloat16(v.z), h3 = __float2bfloat16(v.w);
    __nv_bfloat16 l0 = __float2bfloat16(v.x - __bfloat162float(h0));
    __nv_bfloat16 l1 = __float2bfloat16(v.y - __bfloat162float(h1));
    __nv_bfloat16 l2 = __float2bfloat16(v.z - __bfloat162float(h2));
    __nv_bfloat16 l3 = __float2bfloat16(v.w - __bfloat162float(h3));
    *reinterpret_cast<__nv_bfloat162*>(g_data_hi + i)     = __nv_bfloat162(h0, h1);
    *reinterpret_cast<__nv_bfloat162*>(g_data_hi + i + 2) = __nv_bfloat162(h2, h3);
    *reinterpret_cast<__nv_bfloat162*>(g_data_lo + i)     = __nv_bfloat162(l0, l1);
    *reinterpret_cast<__nv_bfloat162*>(g_data_lo + i + 2) = __nv_bfloat162(l2, l3);
}

__global__ __launch_bounds__(256) void decomp_A_kernel(const float* __restrict__ A) {
    int i = blockIdx.x * 256 + threadIdx.x;
    float v = A[i];
    __nv_bfloat16 h = __float2bfloat16(v);
    __nv_bfloat16 l = __float2bfloat16(v - __bfloat162float(h));
    g_A_hi[i] = h;
    g_A_lo[i] = l;
    int d = i >> 9, k = i & 511;
    g_AT_hi[k * 512 + d] = h;
    g_AT_lo[k * 512 + d] = l;
}

// ---------------------------------------------------------------------------
// LUT build: for each k, lut[j] = searchsorted_left(xx[k,:], -4 + j*12/1024).
// ---------------------------------------------------------------------------
__global__ __launch_bounds__(256) void lut_kernel(const float* __restrict__ xx) {
    __shared__ float sx[MKNOT];
    const int k = blockIdx.x;
    const int tid = threadIdx.x;
    if (tid < MKNOT) sx[tid] = xx[(size_t)k * MKNOT + tid];
    __syncthreads();
    for (int j = tid; j < LUTN; j += 256) {
        const float gx = -4.0f + (float)j * (12.0f / LUTN);
        int lo = 0, hi = MKNOT;
        while (lo < hi) {
            int mid = (lo + hi) >> 1;
            if (sx[mid] < gx) lo = mid + 1; else hi = mid;
        }
        g_lut[(size_t)k * LUTN + j] = (uint8_t)lo;
    }
}

// ---------------------------------------------------------------------------
// HMMA GEMM mainloop, phase-paired: D[128,128] over K'=1536 in 16 chunks.
// Chunks 0-7  (dual):   A=aHi[koff], B = bHi[koff] and bLo[koff] (A-frags reused)
// Chunks 8-15 (single): A=aLo[koff], B = bHi[koff]
// Stage = A 16KB + B 32KB = 48KB; double-buffered = 96KB; 2 CTAs/SM.
// ---------------------------------------------------------------------------
#define STAGE_BYTES 49152
#define GEMM_SMEM   (2 * STAGE_BYTES)

__device__ __forceinline__ void issue_chunk(uint32_t sbase, int buf, int c, int tid,
        const __nv_bfloat16* aHi, const __nv_bfloat16* aLo,
        const __nv_bfloat16* bHi, const __nv_bfloat16* bLo) {
    const bool dual = (c < 8);
    const int koff = (c & 7) * 64;
    const __nv_bfloat16* a = dual ? aHi : aLo;
    uint32_t abase = sbase + buf * STAGE_BYTES;
    uint32_t bbase = abase + 16384;
    #pragma unroll
    for (int it = 0; it < 4; ++it) {          // A tile: 128 rows x 128B
        int i = tid + it * 256;
        int r = i >> 3, cc = i & 7;
        CP_ASYNC16(abase + r * 128 + ((cc ^ (r & 7)) << 4),
                   a + (size_t)r * 512 + koff + cc * 8);
    }
    #pragma unroll
    for (int it = 0; it < 4; ++it) {          // B-hi tile
        int i = tid + it * 256;
        int r = i >> 3, cc = i & 7;
        CP_ASYNC16(bbase + r * 128 + ((cc ^ (r & 7)) << 4),
                   bHi + (size_t)r * 512 + koff + cc * 8);
    }
    if (dual) {
        #pragma unroll
        for (int it = 0; it < 4; ++it) {      // B-lo tile (dual chunks only)
            int i = tid + it * 256;
            int r = i >> 3, cc = i & 7;
            CP_ASYNC16(bbase + 16384 + r * 128 + ((cc ^ (r & 7)) << 4),
                       bLo + (size_t)r * 512 + koff + cc * 8);
        }
    }
}

__device__ __forceinline__ void load_bfrag(uint32_t bbase, int s, int lane, int wn,
                                           int grp, uint32_t bf[4][2]) {
    #pragma unroll
    for (int nt2 = 0; nt2 < 2; ++nt2) {
        int rr = wn * 32 + nt2 * 16 + (lane & 7) + ((grp >> 1) << 3);
        int cc = s * 2 + (grp & 1);
        uint32_t tmp[4];
        ldsm_x4(tmp, bbase + rr * 128 + ((cc ^ (rr & 7)) << 4));
        bf[nt2 * 2][0] = tmp[0];     bf[nt2 * 2][1] = tmp[1];
        bf[nt2 * 2 + 1][0] = tmp[2]; bf[nt2 * 2 + 1][1] = tmp[3];
    }
}

__device__ __forceinline__ void compute_chunk(uint32_t sbase, int buf, bool dual,
                                              int lane, int wm, int wn, float acc[4][4][4]) {
    uint32_t abase = sbase + buf * STAGE_BYTES;
    uint32_t bbase = abase + 16384;
    const int grp = lane >> 3;
    #pragma unroll
    for (int s = 0; s < 4; ++s) {
        uint32_t af[4][4];
        #pragma unroll
        for (int mt = 0; mt < 4; ++mt) {
            int rr = wm * 64 + mt * 16 + (lane & 7) + ((grp & 1) << 3);
            int cc = s * 2 + (grp >> 1);
            ldsm_x4(af[mt], abase + rr * 128 + ((cc ^ (rr & 7)) << 4));
        }
        uint32_t bf[4][2];
        load_bfrag(bbase, s, lane, wn, grp, bf);
        #pragma unroll
        for (int mt = 0; mt < 4; ++mt)
            #pragma unroll
            for (int nt = 0; nt < 4; ++nt)
                mma16816(acc[mt][nt], af[mt], bf[nt]);
        if (dual) {   // reuse af against the B-lo tile
            uint32_t bf2[4][2];
            load_bfrag(bbase + 16384, s, lane, wn, grp, bf2);
            #pragma unroll
            for (int mt = 0; mt < 4; ++mt)
                #pragma unroll
                for (int nt = 0; nt < 4; ++nt)
                    mma16816(acc[mt][nt], af[mt], bf2[nt]);
        }
    }
}

__device__ __forceinline__ void gemm_mainloop(const __nv_bfloat16* aHi, const __nv_bfloat16* aLo,
                                              const __nv_bfloat16* bHi, const __nv_bfloat16* bLo,
                                              uint32_t sbase, int tid, int lane, int wm, int wn,
                                              float acc[4][4][4]) {
    #pragma unroll
    for (int mt = 0; mt < 4; ++mt)
        #pragma unroll
        for (int nt = 0; nt < 4; ++nt)
            #pragma unroll
            for (int r = 0; r < 4; ++r) acc[mt][nt][r] = 0.f;

    issue_chunk(sbase, 0, 0, tid, aHi, aLo, bHi, bLo);
    CP_COMMIT();
    int buf = 0;
    for (int c = 0; c < 16; ++c) {
        if (c + 1 < 16) {
            issue_chunk(sbase, buf ^ 1, c + 1, tid, aHi, aLo, bHi, bLo);
            CP_COMMIT();
            CP_WAIT(1);
        } else {
            CP_WAIT(0);
        }
        __syncthreads();
        compute_chunk(sbase, buf, c < 8, lane, wm, wn, acc);
        __syncthreads();
        buf ^= 1;
    }
}

// Stage one 64-column half of D (columns c in [half*64, half*64+64)) into
// smem as sD[c - half*64][m] (stride 132), by the 4 warps owning that half.
__device__ __forceinline__ void stage_half(float* sD, const float acc[4][4][4],
                                           int wm, int wn, int lane, int half) {
    if ((wn >> 1) == half) {
        #pragma unroll
        for (int mt = 0; mt < 4; ++mt)
            #pragma unroll
            for (int nt = 0; nt < 4; ++nt) {
                int r0 = wm * 64 + mt * 16 + (lane >> 2);
                int c0 = (wn & 1) * 32 + nt * 8 + (lane & 3) * 2;
                sD[(c0    ) * 132 + r0    ] = acc[mt][nt][0];
                sD[(c0 + 1) * 132 + r0    ] = acc[mt][nt][1];
                sD[(c0    ) * 132 + r0 + 8] = acc[mt][nt][2];
                sD[(c0 + 1) * 132 + r0 + 8] = acc[mt][nt][3];
            }
    }
}

__global__ __launch_bounds__(256, 2) void gemm1_kernel() {
    extern __shared__ char smem[];
    const int k0 = blockIdx.x * 128;
    const int n0 = blockIdx.y * 128;
    const int tid = threadIdx.x;
    const int lane = tid & 31, wid = tid >> 5;
    const int wm = wid & 1, wn = wid >> 1;
    uint32_t sbase = smem_u32(smem);

    float acc[4][4][4];
    gemm_mainloop(g_data_hi + (size_t)n0 * 512, g_data_lo + (size_t)n0 * 512,
                  g_AT_hi + (size_t)k0 * 512, g_AT_lo + (size_t)k0 * 512,
                  sbase, tid, lane, wm, wn, acc);

    float* sD = (float*)smem;
    #pragma unroll
    for (int half = 0; half < 2; ++half) {
        stage_half(sD, acc, wm, wn, lane, half);
        __syncthreads();
        #pragma unroll
        for (int it = 0; it < 8; ++it) {
            int idx = tid + it * 256;
            int nn = idx >> 5, mm = (idx & 31) * 4;
            float4 v = *reinterpret_cast<const float4*>(sD + nn * 132 + mm);
            *reinterpret_cast<float4*>(&g_x[(size_t)(k0 + half * 64 + nn) * NROWS + n0 + mm]) = v;
        }
        __syncthreads();
    }
}

__global__ __launch_bounds__(256, 2) void gemm2_kernel(const float* __restrict__ data,
                                                       float* __restrict__ out) {
    extern __shared__ char smem[];
    const int d0 = blockIdx.x * 128;
    const int n0 = blockIdx.y * 128;
    const int tid = threadIdx.x;
    const int lane = tid & 31, wid = tid >> 5;
    const int wm = wid & 1, wn = wid >> 1;
    uint32_t sbase = smem_u32(smem);

    float acc[4][4][4];
    gemm_mainloop(g_A_hi + (size_t)d0 * 512, g_A_lo + (size_t)d0 * 512,
                  g_t_hi + (size_t)n0 * 512, g_t_lo + (size_t)n0 * 512,
                  sbase, tid, lane, wm, wn, acc);

    float* sD = (float*)smem;
    #pragma unroll
    for (int half = 0; half < 2; ++half) {
        stage_half(sD, acc, wm, wn, lane, half);
        __syncthreads();
        #pragma unroll
        for (int it = 0; it < 8; ++it) {
            int idx = tid + it * 256;
            int nn = idx >> 5, mm = (idx & 31) * 4;
            size_t gi = (size_t)(n0 + half * 64 + nn) * NDIMS + d0 + mm;
            float4 v = *reinterpret_cast<const float4*>(sD + nn * 132 + mm);
            float4 dv = *reinterpret_cast<const float4*>(data + gi);
            v.x += dv.x; v.y += dv.y; v.z += dv.z; v.w += dv.w;
            *reinterpret_cast<float4*>(out + gi) = v;
        }
        __syncthreads();
    }
}

// ---------------------------------------------------------------------------
// Spline (LUT bracket): block = 8 k x 1024 n. Grid (64, 64).
// ---------------------------------------------------------------------------
__global__ __launch_bounds__(256) void spline_kernel(const float* __restrict__ xx,
                                                     const float* __restrict__ yy,
                                                     const float* __restrict__ delta) {
    __shared__ float sxx[8 * MKNOT], syy[8 * MKNOT], sdl[8 * MKNOT];
    __shared__ uint8_t slut[8 * LUTN];
    __shared__ __align__(16) __nv_bfloat16 sth[64 * 8], stl[64 * 8];
    __shared__ float sred[256];

    const int kg = blockIdx.x;
    const int ng = blockIdx.y;
    const int k0 = kg * 8;
    const int tid = threadIdx.x;

    for (int i = tid; i < 8 * MKNOT; i += 256) {
        int kl = i / MKNOT, m = i - kl * MKNOT;
        size_t gi = (size_t)(k0 + kl) * MKNOT + m;
        sxx[i] = xx[gi]; syy[i] = yy[gi]; sdl[i] = delta[gi];
    }
    for (int i = tid; i < (8 * LUTN) / 4; i += 256)
        reinterpret_cast<uint32_t*>(slut)[i] =
            reinterpret_cast<const uint32_t*>(g_lut + (size_t)k0 * LUTN)[i];
    __syncthreads();

    const int nl = tid & 63;
    const int kgrp = tid >> 6;

    for (int s = 0; s < 16; ++s) {
        const int n = ng * 1024 + s * 64 + nl;
        float acc = 0.f;
        #pragma unroll
        for (int r = 0; r < 2; ++r) {
            const int kl = r * 4 + kgrp;
            const float* kx = sxx + kl * MKNOT;
            const float* ky = syy + kl * MKNOT;
            const float* kd = sdl + kl * MKNOT;
            const float x = g_x[(size_t)(k0 + kl) * NROWS + n];

            int j = __float2int_rd((x + 4.0f) * LUT_SCALE);
            j = min(max(j, 0), LUTN - 1);
            int idx = (int)slut[kl * LUTN + j];
            if (idx < MKNOT && kx[idx] < x) ++idx;

            const bool below = (idx == 0);
            const bool above = (idx == MKNOT);
            const int b = min(max(idx, 1), MKNOT - 1) - 1;

            const float xk = kx[b], xk1 = kx[b + 1];
            const float yk = ky[b], yk1 = ky[b + 1];
            const float dk = kd[b], dk1 = kd[b + 1];
            const float dxk = xk1 - xk;
            const float dyk = yk1 - yk;
            const float sl = dyk / dxk;
            float xi = (x - xk) / dxk;
            xi = fminf(fmaxf(xi, 0.f), 1.f);
            const float xi1 = 1.f - xi;
            const float denom = sl + (dk1 + dk - 2.f * sl) * xi * xi1;
            float y = yk + dyk * (sl * xi * xi + dk * xi * xi1) / denom;
            const float num = dk1 * xi * xi + 2.f * sl * xi * xi1 + dk * xi1 * xi1;
            float logd = logf((sl * sl) * num / (denom * denom));
            if (below) { y = ky[0] + kd[0] * (x - kx[0]); logd = logf(kd[0]); }
            if (above) { y = ky[MKNOT - 1] + kd[MKNOT - 1] * (x - kx[MKNOT - 1]); logd = logf(kd[MKNOT - 1]); }

            const float t = y - x;
            acc += logd;
            __nv_bfloat16 h = __float2bfloat16(t);
            __nv_bfloat16 l = __float2bfloat16(t - __bfloat162float(h));
            sth[nl * 8 + kl] = h;
            stl[nl * 8 + kl] = l;
        }
        sred[tid] = acc;
        __syncthreads();

        if (tid < 64) {
            uint4 hv = *reinterpret_cast<const uint4*>(sth + tid * 8);
            *reinterpret_cast<uint4*>(g_t_hi + (size_t)(ng * 1024 + s * 64 + tid) * KDIM + k0) = hv;
        } else if (tid < 128) {
            int row = tid - 64;
            uint4 lv = *reinterpret_cast<const uint4*>(stl + row * 8);
            *reinterpret_cast<uint4*>(g_t_lo + (size_t)(ng * 1024 + s * 64 + row) * KDIM + k0) = lv;
        } else if (tid < 192) {
            int row = tid - 128;
            float p = sred[row] + sred[64 + row] + sred[128 + row] + sred[192 + row];
            g_partial[(size_t)kg * NROWS + ng * 1024 + s * 64 + row] = p;
        }
        __syncthreads();
    }
}

__global__ __launch_bounds__(256) void reduce_kernel(float* __restrict__ logj) {
    const int n = blockIdx.x * 256 + threadIdx.x;
    float s = 0.f;
    #pragma unroll
    for (int g = 0; g < 64; ++g) s += g_partial[(size_t)g * NROWS + n];
    logj[n] = s;
}

// ---------------------------------------------------------------------------
extern "C" void kernel_launch(void* const* d_in, const int* in_sizes, int n_in,
                              void* d_out, int out_size) {
    (void)in_sizes; (void)n_in; (void)out_size;
    const float* data  = (const float*)d_in[0];
    const float* A     = (const float*)d_in[1];
    const float* xx    = (const float*)d_in[2];
    const float* yy    = (const float*)d_in[3];
    const float* delta = (const float*)d_in[4];
    float* out  = (float*)d_out;
    float* logj = out + (size_t)NROWS * NDIMS;

    cudaFuncSetAttribute(gemm1_kernel, cudaFuncAttributeMaxDynamicSharedMemorySize, GEMM_SMEM);
    cudaFuncSetAttribute(gemm2_kernel, cudaFuncAttributeMaxDynamicSharedMemorySize, GEMM_SMEM);
    cudaFuncSetAttribute(gemm1_kernel, cudaFuncAttributePreferredSharedMemoryCarveout,
                         cudaSharedmemCarveoutMaxShared);
    cudaFuncSetAttribute(gemm2_kernel, cudaFuncAttributePreferredSharedMemoryCarveout,
                         cudaSharedmemCarveoutMaxShared);

    decomp_data_kernel<<<((size_t)NROWS * NDIMS) / 1024, 256>>>(data);
    decomp_A_kernel<<<(KDIM * NDIMS) / 256, 256>>>(A);
    lut_kernel<<<KDIM, 256>>>(xx);
    gemm1_kernel<<<dim3(4, NROWS / 128), 256, GEMM_SMEM>>>();
    spline_kernel<<<dim3(64, 64), 256>>>(xx, yy, delta);
    reduce_kernel<<<NROWS / 256, 256>>>(logj);
    gemm2_kernel<<<dim3(4, NROWS / 128), 256, GEMM_SMEM>>>(data, out);
}

// round 13
// speedup vs baseline: 2.8151x; 1.0902x over previous
#include <cuda_runtime.h>
#include <cuda_bf16.h>
#include <cstdint>

#define NROWS 65536
#define NDIMS 512
#define KDIM  512
#define MKNOT 200
#define LUTN  1024
#define LUT_SCALE (1024.0f / 12.0f)

// ---------------------------------------------------------------------------
// Device scratch (allocation-free)
// ---------------------------------------------------------------------------
__device__ __align__(16) float         g_x[(size_t)KDIM * NROWS];       // data0^T (K x N)
__device__ __align__(16) __nv_bfloat16 g_data_hi[(size_t)NROWS * NDIMS];
__device__ __align__(16) __nv_bfloat16 g_data_lo[(size_t)NROWS * NDIMS];
__device__ __align__(16) __nv_bfloat16 g_t_hi[(size_t)KDIM * NROWS];    // (K x N) now
__device__ __align__(16) __nv_bfloat16 g_t_lo[(size_t)KDIM * NROWS];
__device__ __align__(16) __nv_bfloat16 g_A_hi[KDIM * NDIMS];            // [d][k]
__device__ __align__(16) __nv_bfloat16 g_A_lo[KDIM * NDIMS];
__device__ __align__(16) __nv_bfloat16 g_AT_hi[KDIM * NDIMS];           // [k][d]
__device__ __align__(16) __nv_bfloat16 g_AT_lo[KDIM * NDIMS];
__device__ __align__(16) float         g_partial[64 * NROWS];
__device__ __align__(16) uint8_t       g_lut[(size_t)KDIM * LUTN];

// ---------------------------------------------------------------------------
// PTX helpers (sm_80-level: legal on baseline compute_103 target)
// ---------------------------------------------------------------------------
__device__ __forceinline__ uint32_t smem_u32(const void* p) {
    uint32_t a;
    asm("{ .reg .u64 t; cvta.to.shared.u64 t, %1; cvt.u32.u64 %0, t; }" : "=r"(a) : "l"(p));
    return a;
}
#define CP_ASYNC16(dst, src) \
    asm volatile("cp.async.cg.shared.global [%0], [%1], 16;" :: "r"(dst), "l"(src))
#define CP_COMMIT() asm volatile("cp.async.commit_group;" ::: "memory")
#define CP_WAIT(n)  asm volatile("cp.async.wait_group %0;" :: "n"(n) : "memory")

__device__ __forceinline__ void ldsm_x4(uint32_t* r, uint32_t addr) {
    asm volatile("ldmatrix.sync.aligned.m8n8.x4.shared.b16 {%0,%1,%2,%3}, [%4];"
                 : "=r"(r[0]), "=r"(r[1]), "=r"(r[2]), "=r"(r[3]) : "r"(addr));
}
__device__ __forceinline__ void ldsm_x4_trans(uint32_t* r, uint32_t addr) {
    asm volatile("ldmatrix.sync.aligned.m8n8.x4.trans.shared.b16 {%0,%1,%2,%3}, [%4];"
                 : "=r"(r[0]), "=r"(r[1]), "=r"(r[2]), "=r"(r[3]) : "r"(addr));
}
__device__ __forceinline__ void mma16816(float* d, const uint32_t* a, const uint32_t* b) {
    asm volatile(
        "mma.sync.aligned.m16n8k16.row.col.f32.bf16.bf16.f32 "
        "{%0,%1,%2,%3}, {%4,%5,%6,%7}, {%8,%9}, {%0,%1,%2,%3};"
        : "+f"(d[0]), "+f"(d[1]), "+f"(d[2]), "+f"(d[3])
        : "r"(a[0]), "r"(a[1]), "r"(a[2]), "r"(a[3]), "r"(b[0]), "r"(b[1]));
}

// ---------------------------------------------------------------------------
// Split decomposition
// ---------------------------------------------------------------------------
__global__ __launch_bounds__(256) void decomp_data_kernel(const float* __restrict__ data) {
    size_t i = ((size_t)blockIdx.x * 256 + threadIdx.x) * 4;
    float4 v = *reinterpret_cast<const float4*>(data + i);
    __nv_bfloat16 h0 = __float2bfloat16(v.x), h1 = __float2bfloat16(v.y);
    __nv_bfloat16 h2 = __float2bfloat16(v.z), h3 = __float2bfloat16(v.w);
    __nv_bfloat16 l0 = __float2bfloat16(v.x - __bfloat162float(h0));
    __nv_bfloat16 l1 = __float2bfloat16(v.y - __bfloat162float(h1));
    __nv_bfloat16 l2 = __float2bfloat16(v.z - __bfloat162float(h2));
    __nv_bfloat16 l3 = __float2bfloat16(v.w - __bfloat162float(h3));
    *reinterpret_cast<__nv_bfloat162*>(g_data_hi + i)     = __nv_bfloat162(h0, h1);
    *reinterpret_cast<__nv_bfloat162*>(g_data_hi + i + 2) = __nv_bfloat162(h2, h3);
    *reinterpret_cast<__nv_bfloat162*>(g_data_lo + i)     = __nv_bfloat162(l0, l1);
    *reinterpret_cast<__nv_bfloat162*>(g_data_lo + i + 2) = __nv_bfloat162(l2, l3);
}

__global__ __launch_bounds__(256) void decomp_A_kernel(const float* __restrict__ A) {
    int i = blockIdx.x * 256 + threadIdx.x;
    float v = A[i];
    __nv_bfloat16 h = __float2bfloat16(v);
    __nv_bfloat16 l = __float2bfloat16(v - __bfloat162float(h));
    g_A_hi[i] = h;
    g_A_lo[i] = l;
    int d = i >> 9, k = i & 511;
    g_AT_hi[k * 512 + d] = h;
    g_AT_lo[k * 512 + d] = l;
}

// ---------------------------------------------------------------------------
// LUT build
// ---------------------------------------------------------------------------
__global__ __launch_bounds__(256) void lut_kernel(const float* __restrict__ xx) {
    __shared__ float sx[MKNOT];
    const int k = blockIdx.x;
    const int tid = threadIdx.x;
    if (tid < MKNOT) sx[tid] = xx[(size_t)k * MKNOT + tid];
    __syncthreads();
    for (int j = tid; j < LUTN; j += 256) {
        const float gx = -4.0f + (float)j * (12.0f / LUTN);
        int lo = 0, hi = MKNOT;
        while (lo < hi) {
            int mid = (lo + hi) >> 1;
            if (sx[mid] < gx) lo = mid + 1; else hi = mid;
        }
        g_lut[(size_t)k * LUTN + j] = (uint8_t)lo;
    }
}

// ---------------------------------------------------------------------------
// HMMA GEMM mainloop, phase-paired: D[128,128] over K'=1536 in 16 chunks.
// TB=false: B from (N,K) K-major rows (gemm1, B = AT).
// TB=true : B from (K,N), 64 k-rows x 256B tiles, ldmatrix.trans (gemm2, B = t).
// Stage = A 16KB + B 16KB (+16KB dual) = 48KB; double-buffered = 96KB; 2 CTAs/SM.
// ---------------------------------------------------------------------------
#define STAGE_BYTES 49152
#define GEMM_SMEM   (2 * STAGE_BYTES)

template <bool TB>
__device__ __forceinline__ void issue_chunk(uint32_t sbase, int buf, int c, int tid,
        const __nv_bfloat16* aHi, const __nv_bfloat16* aLo,
        const __nv_bfloat16* bHi, const __nv_bfloat16* bLo) {
    const bool dual = (c < 8);
    const int koff = (c & 7) * 64;
    const __nv_bfloat16* a = dual ? aHi : aLo;
    uint32_t abase = sbase + buf * STAGE_BYTES;
    uint32_t bbase = abase + 16384;
    #pragma unroll
    for (int it = 0; it < 4; ++it) {          // A tile: 128 rows x 128B (K-major)
        int i = tid + it * 256;
        int r = i >> 3, cc = i & 7;
        CP_ASYNC16(abase + r * 128 + ((cc ^ (r & 7)) << 4),
                   a + (size_t)r * 512 + koff + cc * 8);
    }
    if (!TB) {
        #pragma unroll
        for (int it = 0; it < 4; ++it) {      // B-hi: 128 n-rows x 128B
            int i = tid + it * 256;
            int r = i >> 3, cc = i & 7;
            CP_ASYNC16(bbase + r * 128 + ((cc ^ (r & 7)) << 4),
                       bHi + (size_t)r * 512 + koff + cc * 8);
        }
        if (dual) {
            #pragma unroll
            for (int it = 0; it < 4; ++it) {
                int i = tid + it * 256;
                int r = i >> 3, cc = i & 7;
                CP_ASYNC16(bbase + 16384 + r * 128 + ((cc ^ (r & 7)) << 4),
                           bLo + (size_t)r * 512 + koff + cc * 8);
            }
        }
    } else {
        #pragma unroll
        for (int it = 0; it < 4; ++it) {      // B-hi: 64 k-rows x 256B from (K,N)
            int i = tid + it * 256;
            int r = i >> 4, cc = i & 15;
            CP_ASYNC16(bbase + r * 256 + ((cc ^ (r & 7)) << 4),
                       bHi + (size_t)(koff + r) * NROWS + cc * 8);
        }
        if (dual) {
            #pragma unroll
            for (int it = 0; it < 4; ++it) {
                int i = tid + it * 256;
                int r = i >> 4, cc = i & 15;
                CP_ASYNC16(bbase + 16384 + r * 256 + ((cc ^ (r & 7)) << 4),
                           bLo + (size_t)(koff + r) * NROWS + cc * 8);
            }
        }
    }
}

template <bool TB>
__device__ __forceinline__ void load_bfrag(uint32_t bbase, int s, int lane, int wn,
                                           int grp, uint32_t bf[4][2]) {
    if (!TB) {
        #pragma unroll
        for (int nt2 = 0; nt2 < 2; ++nt2) {
            int rr = wn * 32 + nt2 * 16 + (lane & 7) + ((grp >> 1) << 3);
            int cc = s * 2 + (grp & 1);
            uint32_t tmp[4];
            ldsm_x4(tmp, bbase + rr * 128 + ((cc ^ (rr & 7)) << 4));
            bf[nt2 * 2][0] = tmp[0];     bf[nt2 * 2][1] = tmp[1];
            bf[nt2 * 2 + 1][0] = tmp[2]; bf[nt2 * 2 + 1][1] = tmp[3];
        }
    } else {
        #pragma unroll
        for (int nt2 = 0; nt2 < 2; ++nt2) {
            int rr = s * 16 + ((grp & 1) << 3) + (lane & 7);     // k-row 0..63
            int un = wn * 4 + nt2 * 2 + (grp >> 1);              // 16B n-unit 0..15
            uint32_t tmp[4];
            ldsm_x4_trans(tmp, bbase + rr * 256 + ((un ^ (rr & 7)) << 4));
            bf[nt2 * 2][0] = tmp[0];     bf[nt2 * 2][1] = tmp[1];
            bf[nt2 * 2 + 1][0] = tmp[2]; bf[nt2 * 2 + 1][1] = tmp[3];
        }
    }
}

template <bool TB>
__device__ __forceinline__ void compute_chunk(uint32_t sbase, int buf, bool dual,
                                              int lane, int wm, int wn, float acc[4][4][4]) {
    uint32_t abase = sbase + buf * STAGE_BYTES;
    uint32_t bbase = abase + 16384;
    const int grp = lane >> 3;
    #pragma unroll
    for (int s = 0; s < 4; ++s) {
        uint32_t af[4][4];
        #pragma unroll
        for (int mt = 0; mt < 4; ++mt) {
            int rr = wm * 64 + mt * 16 + (lane & 7) + ((grp & 1) << 3);
            int cc = s * 2 + (grp >> 1);
            ldsm_x4(af[mt], abase + rr * 128 + ((cc ^ (rr & 7)) << 4));
        }
        uint32_t bf[4][2];
        load_bfrag<TB>(bbase, s, lane, wn, grp, bf);
        #pragma unroll
        for (int mt = 0; mt < 4; ++mt)
            #pragma unroll
            for (int nt = 0; nt < 4; ++nt)
                mma16816(acc[mt][nt], af[mt], bf[nt]);
        if (dual) {   // reuse af against the B-lo tile
            uint32_t bf2[4][2];
            load_bfrag<TB>(bbase + 16384, s, lane, wn, grp, bf2);
            #pragma unroll
            for (int mt = 0; mt < 4; ++mt)
                #pragma unroll
                for (int nt = 0; nt < 4; ++nt)
                    mma16816(acc[mt][nt], af[mt], bf2[nt]);
        }
    }
}

template <bool TB>
__device__ __forceinline__ void gemm_mainloop(const __nv_bfloat16* aHi, const __nv_bfloat16* aLo,
                                              const __nv_bfloat16* bHi, const __nv_bfloat16* bLo,
                                              uint32_t sbase, int tid, int lane, int wm, int wn,
                                              float acc[4][4][4]) {
    #pragma unroll
    for (int mt = 0; mt < 4; ++mt)
        #pragma unroll
        for (int nt = 0; nt < 4; ++nt)
            #pragma unroll
            for (int r = 0; r < 4; ++r) acc[mt][nt][r] = 0.f;

    issue_chunk<TB>(sbase, 0, 0, tid, aHi, aLo, bHi, bLo);
    CP_COMMIT();
    int buf = 0;
    for (int c = 0; c < 16; ++c) {
        if (c + 1 < 16) {
            issue_chunk<TB>(sbase, buf ^ 1, c + 1, tid, aHi, aLo, bHi, bLo);
            CP_COMMIT();
            CP_WAIT(1);
        } else {
            CP_WAIT(0);
        }
        __syncthreads();
        compute_chunk<TB>(sbase, buf, c < 8, lane, wm, wn, acc);
        __syncthreads();
        buf ^= 1;
    }
}

// Stage one 64-column half of D into smem as sD[c][m] stride 132.
__device__ __forceinline__ void stage_half(float* sD, const float acc[4][4][4],
                                           int wm, int wn, int lane, int half) {
    if ((wn >> 1) == half) {
        #pragma unroll
        for (int mt = 0; mt < 4; ++mt)
            #pragma unroll
            for (int nt = 0; nt < 4; ++nt) {
                int r0 = wm * 64 + mt * 16 + (lane >> 2);
                int c0 = (wn & 1) * 32 + nt * 8 + (lane & 3) * 2;
                sD[(c0    ) * 132 + r0    ] = acc[mt][nt][0];
                sD[(c0 + 1) * 132 + r0    ] = acc[mt][nt][1];
                sD[(c0    ) * 132 + r0 + 8] = acc[mt][nt][2];
                sD[(c0 + 1) * 132 + r0 + 8] = acc[mt][nt][3];
            }
    }
}

__global__ __launch_bounds__(256, 2) void gemm1_kernel() {
    extern __shared__ char smem[];
    const int k0 = blockIdx.x * 128;
    const int n0 = blockIdx.y * 128;
    const int tid = threadIdx.x;
    const int lane = tid & 31, wid = tid >> 5;
    const int wm = wid & 1, wn = wid >> 1;
    uint32_t sbase = smem_u32(smem);

    float acc[4][4][4];
    gemm_mainloop<false>(g_data_hi + (size_t)n0 * 512, g_data_lo + (size_t)n0 * 512,
                         g_AT_hi + (size_t)k0 * 512, g_AT_lo + (size_t)k0 * 512,
                         sbase, tid, lane, wm, wn, acc);

    float* sD = (float*)smem;
    #pragma unroll
    for (int half = 0; half < 2; ++half) {
        stage_half(sD, acc, wm, wn, lane, half);
        __syncthreads();
        #pragma unroll
        for (int it = 0; it < 8; ++it) {
            int idx = tid + it * 256;
            int nn = idx >> 5, mm = (idx & 31) * 4;
            float4 v = *reinterpret_cast<const float4*>(sD + nn * 132 + mm);
            *reinterpret_cast<float4*>(&g_x[(size_t)(k0 + half * 64 + nn) * NROWS + n0 + mm]) = v;
        }
        __syncthreads();
    }
}

__global__ __launch_bounds__(256, 2) void gemm2_kernel(const float* __restrict__ data,
                                                       float* __restrict__ out) {
    extern __shared__ char smem[];
    const int d0 = blockIdx.x * 128;
    const int n0 = blockIdx.y * 128;
    const int tid = threadIdx.x;
    const int lane = tid & 31, wid = tid >> 5;
    const int wm = wid & 1, wn = wid >> 1;
    uint32_t sbase = smem_u32(smem);

    float acc[4][4][4];
    gemm_mainloop<true>(g_A_hi + (size_t)d0 * 512, g_A_lo + (size_t)d0 * 512,
                        g_t_hi + n0, g_t_lo + n0,
                        sbase, tid, lane, wm, wn, acc);

    float* sD = (float*)smem;
    #pragma unroll
    for (int half = 0; half < 2; ++half) {
        stage_half(sD, acc, wm, wn, lane, half);
        __syncthreads();
        #pragma unroll
        for (int it = 0; it < 8; ++it) {
            int idx = tid + it * 256;
            int nn = idx >> 5, mm = (idx & 31) * 4;
            size_t gi = (size_t)(n0 + half * 64 + nn) * NDIMS + d0 + mm;
            float4 v = *reinterpret_cast<const float4*>(sD + nn * 132 + mm);
            float4 dv = *reinterpret_cast<const float4*>(data + gi);
            v.x += dv.x; v.y += dv.y; v.z += dv.z; v.w += dv.w;
            *reinterpret_cast<float4*>(out + gi) = v;
        }
        __syncthreads();
    }
}

// ---------------------------------------------------------------------------
// Spline v3: block = 8 k x 1024 n (4 s-iters of 256 n, thread = one n, loops k).
// Fully coalesced t writes into (K,N); no barriers in mainloop.
// ---------------------------------------------------------------------------
__global__ __launch_bounds__(256) void spline_kernel(const float* __restrict__ xx,
                                                     const float* __restrict__ yy,
                                                     const float* __restrict__ delta) {
    __shared__ float sxx[8 * MKNOT], syy[8 * MKNOT], sdl[8 * MKNOT];
    __shared__ uint8_t slut[8 * LUTN];

    const int kg = blockIdx.x;          // 0..63
    const int ng = blockIdx.y;          // 0..63
    const int k0 = kg * 8;
    const int tid = threadIdx.x;

    for (int i = tid; i < 8 * MKNOT; i += 256) {
        int kl = i / MKNOT, m = i - kl * MKNOT;
        size_t gi = (size_t)(k0 + kl) * MKNOT + m;
        sxx[i] = xx[gi]; syy[i] = yy[gi]; sdl[i] = delta[gi];
    }
    for (int i = tid; i < (8 * LUTN) / 4; i += 256)
        reinterpret_cast<uint32_t*>(slut)[i] =
            reinterpret_cast<const uint32_t*>(g_lut + (size_t)k0 * LUTN)[i];
    __syncthreads();

    for (int s = 0; s < 4; ++s) {
        const int n = ng * 1024 + s * 256 + tid;
        float acc = 0.f;
        #pragma unroll 4
        for (int kl = 0; kl < 8; ++kl) {
            const float* kx = sxx + kl * MKNOT;
            const float* ky = syy + kl * MKNOT;
            const float* kd = sdl + kl * MKNOT;
            const size_t gidx = (size_t)(k0 + kl) * NROWS + n;
            const float x = g_x[gidx];

            int j = __float2int_rd((x + 4.0f) * LUT_SCALE);
            j = min(max(j, 0), LUTN - 1);
            int idx = (int)slut[kl * LUTN + j];
            if (idx < MKNOT && kx[idx] < x) ++idx;

            const bool below = (idx == 0);
            const bool above = (idx == MKNOT);
            const int b = min(max(idx, 1), MKNOT - 1) - 1;

            const float xk = kx[b], xk1 = kx[b + 1];
            const float yk = ky[b], yk1 = ky[b + 1];
            const float dk = kd[b], dk1 = kd[b + 1];
            const float dxk = xk1 - xk;
            const float dyk = yk1 - yk;
            const float sl = dyk / dxk;
            float xi = (x - xk) / dxk;
            xi = fminf(fmaxf(xi, 0.f), 1.f);
            const float xi1 = 1.f - xi;
            const float denom = sl + (dk1 + dk - 2.f * sl) * xi * xi1;
            float y = yk + dyk * (sl * xi * xi + dk * xi * xi1) / denom;
            const float num = dk1 * xi * xi + 2.f * sl * xi * xi1 + dk * xi1 * xi1;
            float logd = logf((sl * sl) * num / (denom * denom));
            if (below) { y = ky[0] + kd[0] * (x - kx[0]); logd = logf(kd[0]); }
            if (above) { y = ky[MKNOT - 1] + kd[MKNOT - 1] * (x - kx[MKNOT - 1]); logd = logf(kd[MKNOT - 1]); }

            const float t = y - x;
            acc += logd;
            __nv_bfloat16 h = __float2bfloat16(t);
            __nv_bfloat16 l = __float2bfloat16(t - __bfloat162float(h));
            g_t_hi[gidx] = h;
            g_t_lo[gidx] = l;
        }
        g_partial[(size_t)kg * NROWS + n] = acc;
    }
}

__global__ __launch_bounds__(256) void reduce_kernel(float* __restrict__ logj) {
    const int n = blockIdx.x * 256 + threadIdx.x;
    float s = 0.f;
    #pragma unroll
    for (int g = 0; g < 64; ++g) s += g_partial[(size_t)g * NROWS + n];
    logj[n] = s;
}

// ---------------------------------------------------------------------------
extern "C" void kernel_launch(void* const* d_in, const int* in_sizes, int n_in,
                              void* d_out, int out_size) {
    (void)in_sizes; (void)n_in; (void)out_size;
    const float* data  = (const float*)d_in[0];
    const float* A     = (const float*)d_in[1];
    const float* xx    = (const float*)d_in[2];
    const float* yy    = (const float*)d_in[3];
    const float* delta = (const float*)d_in[4];
    float* out  = (float*)d_out;
    float* logj = out + (size_t)NROWS * NDIMS;

    cudaFuncSetAttribute(gemm1_kernel, cudaFuncAttributeMaxDynamicSharedMemorySize, GEMM_SMEM);
    cudaFuncSetAttribute(gemm2_kernel, cudaFuncAttributeMaxDynamicSharedMemorySize, GEMM_SMEM);
    cudaFuncSetAttribute(gemm1_kernel, cudaFuncAttributePreferredSharedMemoryCarveout,
                         cudaSharedmemCarveoutMaxShared);
    cudaFuncSetAttribute(gemm2_kernel, cudaFuncAttributePreferredSharedMemoryCarveout,
                         cudaSharedmemCarveoutMaxShared);

    decomp_data_kernel<<<((size_t)NROWS * NDIMS) / 1024, 256>>>(data);
    decomp_A_kernel<<<(KDIM * NDIMS) / 256, 256>>>(A);
    lut_kernel<<<KDIM, 256>>>(xx);
    gemm1_kernel<<<dim3(4, NROWS / 128), 256, GEMM_SMEM>>>();
    spline_kernel<<<dim3(64, 64), 256>>>(xx, yy, delta);
    reduce_kernel<<<NROWS / 256, 256>>>(logj);
    gemm2_kernel<<<dim3(4, NROWS / 128), 256, GEMM_SMEM>>>(data, out);
}